// round 13
// baseline (speedup 1.0000x reference)
#include <cuda_runtime.h>
#include <cuda_fp16.h>
#include <cuda_bf16.h>
#include <math.h>
#include <stdint.h>

#define EMBED_DIM 512
#define NUM_HEADS 8
#define HEAD_DIM 64
#define T_LEN 128
#define BATCH 8
#define BH 64
#define SCALING 0.125f
#define LAMBDA 1.0f

// Scratch (allocation-free rule: __device__ globals)
__device__ float g_q[BH * T_LEN * HEAD_DIM];     // [i][t][hd], scaled
__device__ float g_k[BH * T_LEN * HEAD_DIM];
__device__ float g_v[BH * T_LEN * HEAD_DIM];
__device__ float g_attn2[T_LEN * BATCH * EMBED_DIM];  // [t][b][h*64+d]

// ---------------------------------------------------------------------------
// helpers (base ISA only: ldmatrix + mma.sync)
// ---------------------------------------------------------------------------
__device__ __forceinline__ uint32_t smem_u32(const void* p) {
    uint32_t a;
    asm("{ .reg .u64 t; cvta.to.shared.u64 t, %1; cvt.u32.u64 %0, t; }"
        : "=r"(a) : "l"(p));
    return a;
}

__device__ __forceinline__ void ldmatrix_x4(uint32_t& r0, uint32_t& r1,
                                            uint32_t& r2, uint32_t& r3,
                                            uint32_t addr) {
    asm volatile("ldmatrix.sync.aligned.m8n8.x4.shared.b16 {%0,%1,%2,%3}, [%4];"
                 : "=r"(r0), "=r"(r1), "=r"(r2), "=r"(r3) : "r"(addr));
}

__device__ __forceinline__ void mma_f16(float* c, uint32_t a0, uint32_t a1,
                                        uint32_t a2, uint32_t a3,
                                        uint32_t b0, uint32_t b1) {
    asm volatile(
        "mma.sync.aligned.m16n8k16.row.col.f32.f16.f16.f32 "
        "{%0,%1,%2,%3}, {%4,%5,%6,%7}, {%8,%9}, {%0,%1,%2,%3};"
        : "+f"(c[0]), "+f"(c[1]), "+f"(c[2]), "+f"(c[3])
        : "r"(a0), "r"(a1), "r"(a2), "r"(a3), "r"(b0), "r"(b1));
}

// pack two fp32 into f16x2 word: low16 = x0, high16 = x1
__device__ __forceinline__ uint32_t cvt_f16x2(float x1, float x0) {
    uint32_t w;
    asm("cvt.rn.f16x2.f32 %0, %1, %2;" : "=r"(w) : "f"(x1), "f"(x0));
    return w;
}

// hi/lo split of 4 floats into packed f16 words (hi = rn(x), lo = rn(x - hi))
__device__ __forceinline__ void split4(float4 v, uint32_t& h0, uint32_t& h1,
                                       uint32_t& l0, uint32_t& l1) {
    h0 = cvt_f16x2(v.y, v.x);
    h1 = cvt_f16x2(v.w, v.z);
    float hx = __half2float(__ushort_as_half((unsigned short)(h0 & 0xFFFF)));
    float hy = __half2float(__ushort_as_half((unsigned short)(h0 >> 16)));
    float hz = __half2float(__ushort_as_half((unsigned short)(h1 & 0xFFFF)));
    float hw = __half2float(__ushort_as_half((unsigned short)(h1 >> 16)));
    l0 = cvt_f16x2(v.y - hy, v.x - hx);
    l1 = cvt_f16x2(v.w - hw, v.z - hz);
}

// SMEM layout (bytes). Rows padded to 144B (64 f16 + 8 pad) => conflict-free.
#define ROWB 144
#define SM_V     0                /* 128 * 144 = 18432 */
#define SM_QS    18432            /* [128][64] f32 = 32768 */
#define SM_FUSED 51200            /* [64][128] f32 = 32768 */
#define SM_TOTAL 83968

// ---------------------------------------------------------------------------
// Projection GEMM: tensor cores, fp16 hi/lo split, 256 threads, K-SPLIT
// across two 4-warp groups. mode 0 (in-proj): 2-term split (XhWh + XlWh) —
// the dropped XhWl (~3e-4 rel on q/k/v) is masked by tri_main's own fp16
// rounding. mode 1 (out-proj): full 3-term (fp32-accurate, error goes
// straight to the output).
// ---------------------------------------------------------------------------
#define PJ_XH 0
#define PJ_XL 9216
#define PJ_WH 18432
#define PJ_WL 27648
#define PJ_BUF 36864
#define PJ_TOTAL 73728

__global__ __launch_bounds__(256) void gemm_proj_kernel(
    const float* __restrict__ xq, const float* __restrict__ xk,
    const float* __restrict__ xv, const float* __restrict__ W,
    const float* __restrict__ bias, float* __restrict__ outp, int mode)
{
    const int jbase = blockIdx.x * 64;
    const int rbase = blockIdx.y * 64;
    const bool three = (mode != 0);   // 3-term only for out-projection

    int section = 0;
    const float* __restrict__ X;
    if (mode == 0) {
        section = jbase >> 9;
        X = (section == 0) ? xq : (section == 1) ? xk : xv;
    } else {
        X = g_attn2;
    }

    extern __shared__ char psm[];
    const uint32_t sbase = smem_u32(psm);

    const int tid = threadIdx.x;
    const int wid = tid >> 5;
    const int lane = tid & 31;
    const int kgrp = wid >> 2;       // 0: chunks 0-3, 1: chunks 4-7
    const int wg = wid & 3;          // warp within group -> 16-row band

    // load-phase (per group): ltid 0..127, row = ltid/2, half th
    const int ltid = tid & 127;
    const int row = ltid >> 1;
    const int th = (ltid & 1) * 32;
    const float* __restrict__ xsrc = X + (size_t)(rbase + row) * 512 + th;
    const float* __restrict__ wsrc = W + (size_t)(jbase + row) * 512 + th;
    char* mybuf = psm + kgrp * PJ_BUF;
    char* xh = mybuf + PJ_XH + row * ROWB + th * 2;
    char* xl = mybuf + PJ_XL + row * ROWB + th * 2;
    char* wh = mybuf + PJ_WH + row * ROWB + th * 2;
    char* wl = mybuf + PJ_WL + row * ROWB + th * 2;

    // ldmatrix addresses within this group's buffer
    const uint32_t gb = sbase + kgrp * PJ_BUF;
    const uint32_t a_ldh = gb + PJ_XH + (wg * 16 + (lane & 15)) * ROWB +
                           ((lane >= 16) ? 16 : 0);
    const uint32_t a_ldl = a_ldh + (PJ_XL - PJ_XH);
    const uint32_t b_ldh = gb + PJ_WH + (lane & 7) * ROWB + ((lane >> 3) * 16);
    const uint32_t b_ldl = b_ldh + (PJ_WL - PJ_WH);

    float acc[8][4];
#pragma unroll
    for (int n = 0; n < 8; n++)
#pragma unroll
        for (int j = 0; j < 4; j++) acc[n][j] = 0.f;

#pragma unroll 1
    for (int j = 0; j < 4; j++) {
        const int k0 = (kgrp * 4 + j) * 64;
        // load & hi/lo split this group's chunk into its buffer
#pragma unroll
        for (int jj = 0; jj < 32; jj += 4) {
            float4 v4 = *(const float4*)&xsrc[k0 + jj];
            uint32_t h0, h1, l0, l1;
            split4(v4, h0, h1, l0, l1);
            *(uint2*)(xh + jj * 2) = make_uint2(h0, h1);
            *(uint2*)(xl + jj * 2) = make_uint2(l0, l1);
            float4 w4 = *(const float4*)&wsrc[k0 + jj];
            if (three) {
                split4(w4, h0, h1, l0, l1);
                *(uint2*)(wh + jj * 2) = make_uint2(h0, h1);
                *(uint2*)(wl + jj * 2) = make_uint2(l0, l1);
            } else {
                // hi only — no lo split needed for 2-term
                *(uint2*)(wh + jj * 2) =
                    make_uint2(cvt_f16x2(w4.y, w4.x), cvt_f16x2(w4.w, w4.z));
            }
        }
        __syncthreads();

        uint32_t ah[16], al[16];
#pragma unroll
        for (int ks = 0; ks < 4; ks++) {
            ldmatrix_x4(ah[ks * 4 + 0], ah[ks * 4 + 1], ah[ks * 4 + 2],
                        ah[ks * 4 + 3], a_ldh + ks * 32);
            ldmatrix_x4(al[ks * 4 + 0], al[ks * 4 + 1], al[ks * 4 + 2],
                        al[ks * 4 + 3], a_ldl + ks * 32);
        }

#pragma unroll
        for (int nc = 0; nc < 8; nc++) {
            uint32_t bh[8];
            ldmatrix_x4(bh[0], bh[1], bh[2], bh[3], b_ldh + nc * (8 * ROWB));
            ldmatrix_x4(bh[4], bh[5], bh[6], bh[7], b_ldh + nc * (8 * ROWB) + 64);
#pragma unroll
            for (int ks = 0; ks < 4; ks++) {
                mma_f16(acc[nc], ah[ks * 4 + 0], ah[ks * 4 + 1], ah[ks * 4 + 2],
                        ah[ks * 4 + 3], bh[ks * 2], bh[ks * 2 + 1]);
                mma_f16(acc[nc], al[ks * 4 + 0], al[ks * 4 + 1], al[ks * 4 + 2],
                        al[ks * 4 + 3], bh[ks * 2], bh[ks * 2 + 1]);
            }
            if (three) {
                uint32_t bl[8];
                ldmatrix_x4(bl[0], bl[1], bl[2], bl[3], b_ldl + nc * (8 * ROWB));
                ldmatrix_x4(bl[4], bl[5], bl[6], bl[7], b_ldl + nc * (8 * ROWB) + 64);
#pragma unroll
                for (int ks = 0; ks < 4; ks++)
                    mma_f16(acc[nc], ah[ks * 4 + 0], ah[ks * 4 + 1],
                            ah[ks * 4 + 2], ah[ks * 4 + 3],
                            bl[ks * 2], bl[ks * 2 + 1]);
            }
        }
        __syncthreads();
    }

    // cross-group reduction: group 1 spills partial C into group 0's dead
    // buffer region (16KB), group 0 adds and does the epilogue.
    float* red = (float*)psm;
    const int rbidx = ((wg * 32 + lane) * 8) * 4;
    if (kgrp == 1) {
#pragma unroll
        for (int nc = 0; nc < 8; nc++)
            *(float4*)&red[rbidx + nc * 4] =
                make_float4(acc[nc][0], acc[nc][1], acc[nc][2], acc[nc][3]);
    }
    __syncthreads();
    if (kgrp == 0) {
        const int g = lane >> 2;
        const int tig = lane & 3;
        const int r0 = rbase + wg * 16 + g;
#pragma unroll
        for (int nc = 0; nc < 8; nc++) {
            float4 r = *(const float4*)&red[rbidx + nc * 4];
            const int jg = jbase + nc * 8 + 2 * tig;
            const float b0 = bias[jg], b1 = bias[jg + 1];
            float v00 = acc[nc][0] + r.x + b0, v01 = acc[nc][1] + r.y + b1;
            float v10 = acc[nc][2] + r.z + b0, v11 = acc[nc][3] + r.w + b1;
            if (mode == 0) {
                if (section == 0) { v00 *= SCALING; v01 *= SCALING;
                                    v10 *= SCALING; v11 *= SCALING; }
                float* dst = (section == 0) ? g_q : (section == 1) ? g_k : g_v;
                const int jj = jg & 511;
                const int h = jj >> 6;
                const int dp = jj & 63;
#pragma unroll
                for (int rr = 0; rr < 2; rr++) {
                    const int r2 = r0 + rr * 8;
                    const int t = r2 >> 3;
                    const int bb = r2 & 7;
                    float2 val = rr ? make_float2(v10, v11) : make_float2(v00, v01);
                    *(float2*)&dst[(((size_t)(bb * 8 + h)) * 128 + t) * 64 + dp] = val;
                }
            } else {
                *(float2*)&outp[(size_t)r0 * 512 + jg] = make_float2(v00, v01);
                *(float2*)&outp[(size_t)(r0 + 8) * 512 + jg] = make_float2(v10, v11);
            }
        }
    }
}

// ---------------------------------------------------------------------------
// Kernel B v8: fp16 mma.sync trilinear, register-built A fragments, 16 warps,
// software-pipelined bias loads. (frozen — best measured config, R11)
// ---------------------------------------------------------------------------
__global__ __launch_bounds__(512, 1) void tri_main_v8(const float* __restrict__ cbias)
{
    const int head  = blockIdx.x;   // 0..7
    const int ahalf = blockIdx.y;   // 0..1
    const int batch = blockIdx.z;   // 0..7
    const int i = batch * 8 + head;
    const int a0 = ahalf * 64;

    extern __shared__ char smem[];
    const uint32_t sbase = smem_u32(smem);
    float* qs    = (float*)(smem + SM_QS);
    float* fused = (float*)(smem + SM_FUSED);

    const int tid  = threadIdx.x;
    const int wid  = tid >> 5;       // 0..15
    const int lane = tid & 31;
    const int bwin = (wid & 7) * 16; // b-row window
    const int asub = (wid >> 3) * 32;

    const float* __restrict__ qi = g_q + (size_t)i * 8192;
    const float* __restrict__ ki = g_k + (size_t)i * 8192;
    const float* __restrict__ vi = g_v + (size_t)i * 8192;

    // qs <- full q (scaled), needed by prep and final bmm
    for (int idx = tid; idx < 8192; idx += 512) qs[idx] = qi[idx];

    // V -> fp16 padded rows. thread: row=tid/4, 16-elem quarter
    {
        const int row = tid >> 2;
        const int tq = (tid & 3) * 16;
        char* vd = smem + SM_V + row * ROWB;
        const float* src = vi + row * 64 + tq;
#pragma unroll
        for (int j = 0; j < 16; j += 4) {
            uint32_t w0 = cvt_f16x2(src[j + 1], src[j]);
            uint32_t w1 = cvt_f16x2(src[j + 3], src[j + 2]);
            *(uint2*)(vd + (tq + j) * 2) = make_uint2(w0, w1);
        }
    }

    const int g = lane >> 2;       // fragment row group
    const int tig = lane & 3;      // fragment col pair

    // K values this lane needs for A fragments: rows bwin+g, bwin+g+8;
    // cols 16*ks + 2*tig + {0,1,8,9}
    float kr0[16], kr1[16];
    {
        const float* krow0 = ki + (size_t)(bwin + g) * 64;
        const float* krow1 = krow0 + 8 * 64;
#pragma unroll
        for (int ks = 0; ks < 4; ks++) {
            int c = ks * 16 + 2 * tig;
            kr0[ks * 4 + 0] = krow0[c];     kr0[ks * 4 + 1] = krow0[c + 1];
            kr0[ks * 4 + 2] = krow0[c + 8]; kr0[ks * 4 + 3] = krow0[c + 9];
            kr1[ks * 4 + 0] = krow1[c];     kr1[ks * 4 + 1] = krow1[c + 1];
            kr1[ks * 4 + 2] = krow1[c + 8]; kr1[ks * 4 + 3] = krow1[c + 9];
        }
    }
    __syncthreads();

    // V ldmatrix base: x4 tiles = 4 consecutive k-octets of 8 n-rows
    const uint32_t v_ld = sbase + SM_V + (lane & 7) * ROWB + ((lane >> 3) * 16);

    const int browA = bwin + g;
    const int colbase = 2 * tig;
    const float* __restrict__ bias_b = cbias + ((size_t)batch << 21);

#pragma unroll 1
    for (int ap = 0; ap < 16; ap++) {
        const int aA = asub + 2 * ap, aB = aA + 1;

        // ---- build A fragments for both a's directly in registers ----
        uint32_t fa0[16], fa1[16];   // [ks*4 + r]
        {
            const float* qA = qs + (a0 + aA) * 64;
            const float* qB = qA + 64;
#pragma unroll
            for (int ks = 0; ks < 4; ks++) {
                int c = ks * 16 + 2 * tig;
                float2 qa01 = *(const float2*)&qA[c];
                float2 qa89 = *(const float2*)&qA[c + 8];
                float2 qb01 = *(const float2*)&qB[c];
                float2 qb89 = *(const float2*)&qB[c + 8];
                fa0[ks * 4 + 0] = cvt_f16x2(kr0[ks * 4 + 1] * qa01.y, kr0[ks * 4 + 0] * qa01.x);
                fa0[ks * 4 + 1] = cvt_f16x2(kr1[ks * 4 + 1] * qa01.y, kr1[ks * 4 + 0] * qa01.x);
                fa0[ks * 4 + 2] = cvt_f16x2(kr0[ks * 4 + 3] * qa89.y, kr0[ks * 4 + 2] * qa89.x);
                fa0[ks * 4 + 3] = cvt_f16x2(kr1[ks * 4 + 3] * qa89.y, kr1[ks * 4 + 2] * qa89.x);
                fa1[ks * 4 + 0] = cvt_f16x2(kr0[ks * 4 + 1] * qb01.y, kr0[ks * 4 + 0] * qb01.x);
                fa1[ks * 4 + 1] = cvt_f16x2(kr1[ks * 4 + 1] * qb01.y, kr1[ks * 4 + 0] * qb01.x);
                fa1[ks * 4 + 2] = cvt_f16x2(kr0[ks * 4 + 3] * qb89.y, kr0[ks * 4 + 2] * qb89.x);
                fa1[ks * 4 + 3] = cvt_f16x2(kr1[ks * 4 + 3] * qb89.y, kr1[ks * 4 + 2] * qb89.x);
            }
        }

        const float* __restrict__ bpA =
            bias_b + ((size_t)(a0 + aA) << 14) + (size_t)browA * 128;
        const float* __restrict__ bpB = bpA + (1 << 14);
        float psA0 = 0.f, psA1 = 0.f, pmA0 = -1e30f, pmA1 = -1e30f;
        float psB0 = 0.f, psB1 = 0.f, pmB0 = -1e30f, pmB1 = -1e30f;

        // prefetch bias for nc=0
        float2 nA0 = *(const float2*)&bpA[colbase];
        float2 nA1 = *(const float2*)&bpA[8 * 128 + colbase];
        float2 nB0 = *(const float2*)&bpB[colbase];
        float2 nB1 = *(const float2*)&bpB[8 * 128 + colbase];

#pragma unroll 2
        for (int nc = 0; nc < 16; nc++) {
            float2 bA0 = nA0, bA1 = nA1, bB0 = nB0, bB1 = nB1;
            if (nc < 15) {
                const int col = (nc + 1) * 8 + colbase;
                nA0 = *(const float2*)&bpA[col];
                nA1 = *(const float2*)&bpA[8 * 128 + col];
                nB0 = *(const float2*)&bpB[col];
                nB1 = *(const float2*)&bpB[8 * 128 + col];
            }
            uint32_t b[8];
            ldmatrix_x4(b[0], b[1], b[2], b[3], v_ld + nc * (8 * ROWB));
            ldmatrix_x4(b[4], b[5], b[6], b[7], v_ld + nc * (8 * ROWB) + 64);
            float c0[4] = {0.f, 0.f, 0.f, 0.f};
            float c1[4] = {0.f, 0.f, 0.f, 0.f};
#pragma unroll
            for (int ks = 0; ks < 4; ks++) {
                mma_f16(c0, fa0[ks * 4 + 0], fa0[ks * 4 + 1], fa0[ks * 4 + 2],
                        fa0[ks * 4 + 3], b[ks * 2], b[ks * 2 + 1]);
                mma_f16(c1, fa1[ks * 4 + 0], fa1[ks * 4 + 1], fa1[ks * 4 + 2],
                        fa1[ks * 4 + 3], b[ks * 2], b[ks * 2 + 1]);
            }
            {
                float s0 = c0[0] + bA0.x, s1 = c0[1] + bA0.y;
                float s2 = c0[2] + bA1.x, s3 = c0[3] + bA1.y;
                psA0 += s0 + s1; psA1 += s2 + s3;
                pmA0 = fmaxf(pmA0, fmaxf(s0, s1));
                pmA1 = fmaxf(pmA1, fmaxf(s2, s3));
            }
            {
                float s0 = c1[0] + bB0.x, s1 = c1[1] + bB0.y;
                float s2 = c1[2] + bB1.x, s3 = c1[3] + bB1.y;
                psB0 += s0 + s1; psB1 += s2 + s3;
                pmB0 = fmaxf(pmB0, fmaxf(s0, s1));
                pmB1 = fmaxf(pmB1, fmaxf(s2, s3));
            }
        }
        // quad reduce (cols spread over 4 tig lanes)
#pragma unroll
        for (int off = 1; off <= 2; off <<= 1) {
            psA0 += __shfl_xor_sync(0xffffffffu, psA0, off);
            psA1 += __shfl_xor_sync(0xffffffffu, psA1, off);
            psB0 += __shfl_xor_sync(0xffffffffu, psB0, off);
            psB1 += __shfl_xor_sync(0xffffffffu, psB1, off);
            pmA0 = fmaxf(pmA0, __shfl_xor_sync(0xffffffffu, pmA0, off));
            pmA1 = fmaxf(pmA1, __shfl_xor_sync(0xffffffffu, pmA1, off));
            pmB0 = fmaxf(pmB0, __shfl_xor_sync(0xffffffffu, pmB0, off));
            pmB1 = fmaxf(pmB1, __shfl_xor_sync(0xffffffffu, pmB1, off));
        }
        if (tig == 0) {
            fused[aA * 128 + browA]     = psA0 * (1.0f / 128.0f) + pmA0;
            fused[aA * 128 + browA + 8] = psA1 * (1.0f / 128.0f) + pmA1;
            fused[aB * 128 + browA]     = psB0 * (1.0f / 128.0f) + pmB0;
            fused[aB * 128 + browA + 8] = psB1 * (1.0f / 128.0f) + pmB1;
        }
    }
    __syncthreads();

    // Softmax over b for each of the 64 rows (one warp per row, round-robin)
    for (int a = wid; a < 64; a += 16) {
        float4 fv = *(float4*)&fused[a * 128 + lane * 4];
        float m = fmaxf(fmaxf(fv.x, fv.y), fmaxf(fv.z, fv.w));
#pragma unroll
        for (int off = 16; off >= 1; off >>= 1)
            m = fmaxf(m, __shfl_xor_sync(0xffffffffu, m, off));
        float e0 = __expf(fv.x - m), e1 = __expf(fv.y - m);
        float e2 = __expf(fv.z - m), e3 = __expf(fv.w - m);
        float s = (e0 + e1) + (e2 + e3);
#pragma unroll
        for (int off = 16; off >= 1; off >>= 1)
            s += __shfl_xor_sync(0xffffffffu, s, off);
        float inv = 1.0f / s;
        *(float4*)&fused[a * 128 + lane * 4] =
            make_float4(e0 * inv, e1 * inv, e2 * inv, e3 * inv);
    }
    __syncthreads();

    // attn[a, :] = sum_b w[a,b] q[b,:]; thread: a=tid/8 (64 rows), 8 cols
    {
        int a = tid >> 3;
        int dg = (tid & 7) * 8;
        float o[8];
#pragma unroll
        for (int j = 0; j < 8; j++) o[j] = 0.f;
        const float* wrow = fused + a * 128;
#pragma unroll 4
        for (int b = 0; b < 128; b++) {
            float wb = wrow[b];
            const float* qr = qs + b * 64 + dg;
            float4 q0 = *(const float4*)&qr[0];
            float4 q1 = *(const float4*)&qr[4];
            o[0] += wb * q0.x; o[1] += wb * q0.y;
            o[2] += wb * q0.z; o[3] += wb * q0.w;
            o[4] += wb * q1.x; o[5] += wb * q1.y;
            o[6] += wb * q1.z; o[7] += wb * q1.w;
        }
        int t = a0 + a;
        float* dst = g_attn2 + ((size_t)t * 8 + batch) * 512 + head * 64 + dg;
        *(float4*)&dst[0] = make_float4(o[0], o[1], o[2], o[3]);
        *(float4*)&dst[4] = make_float4(o[4], o[5], o[6], o[7]);
    }
}

// ---------------------------------------------------------------------------
extern "C" void kernel_launch(void* const* d_in, const int* in_sizes, int n_in,
                              void* d_out, int out_size)
{
    const float* query = (const float*)d_in[0];
    const float* key   = (const float*)d_in[1];
    const float* value = (const float*)d_in[2];
    const float* cbias = (const float*)d_in[3];
    const float* ipw   = (const float*)d_in[4];
    const float* ipb   = (const float*)d_in[5];
    const float* outw  = (const float*)d_in[6];
    const float* outb  = (const float*)d_in[7];
    float* out = (float*)d_out;

    cudaFuncSetAttribute(gemm_proj_kernel,
                         cudaFuncAttributeMaxDynamicSharedMemorySize, PJ_TOTAL);
    // in-projection: 2-term split (error masked by tri_main's fp16 rounding)
    gemm_proj_kernel<<<dim3(24, 16), 256, PJ_TOTAL>>>(query, key, value, ipw,
                                                      ipb, nullptr, 0);

    cudaFuncSetAttribute(tri_main_v8,
                         cudaFuncAttributeMaxDynamicSharedMemorySize, SM_TOTAL);
    tri_main_v8<<<dim3(8, 2, 8), 512, SM_TOTAL>>>(cbias);

    // out-projection: 3-term split (fp32-accurate)
    gemm_proj_kernel<<<dim3(8, 16), 256, PJ_TOTAL>>>(nullptr, nullptr,
                                                     nullptr, outw, outb,
                                                     out, 1);
}

// round 14
// speedup vs baseline: 1.0198x; 1.0198x over previous
#include <cuda_runtime.h>
#include <cuda_fp16.h>
#include <cuda_bf16.h>
#include <math.h>
#include <stdint.h>

#define EMBED_DIM 512
#define NUM_HEADS 8
#define HEAD_DIM 64
#define T_LEN 128
#define BATCH 8
#define BH 64
#define SCALING 0.125f
#define LAMBDA 1.0f

// Scratch (allocation-free rule: __device__ globals)
__device__ float g_q[BH * T_LEN * HEAD_DIM];     // [i][t][hd], scaled
__device__ float g_k[BH * T_LEN * HEAD_DIM];
__device__ float g_v[BH * T_LEN * HEAD_DIM];
__device__ float g_attn2[T_LEN * BATCH * EMBED_DIM];  // [t][b][h*64+d]

// ---------------------------------------------------------------------------
// helpers (base ISA only: ldmatrix + mma.sync)
// ---------------------------------------------------------------------------
__device__ __forceinline__ uint32_t smem_u32(const void* p) {
    uint32_t a;
    asm("{ .reg .u64 t; cvta.to.shared.u64 t, %1; cvt.u32.u64 %0, t; }"
        : "=r"(a) : "l"(p));
    return a;
}

__device__ __forceinline__ void ldmatrix_x4(uint32_t& r0, uint32_t& r1,
                                            uint32_t& r2, uint32_t& r3,
                                            uint32_t addr) {
    asm volatile("ldmatrix.sync.aligned.m8n8.x4.shared.b16 {%0,%1,%2,%3}, [%4];"
                 : "=r"(r0), "=r"(r1), "=r"(r2), "=r"(r3) : "r"(addr));
}

__device__ __forceinline__ void mma_f16(float* c, uint32_t a0, uint32_t a1,
                                        uint32_t a2, uint32_t a3,
                                        uint32_t b0, uint32_t b1) {
    asm volatile(
        "mma.sync.aligned.m16n8k16.row.col.f32.f16.f16.f32 "
        "{%0,%1,%2,%3}, {%4,%5,%6,%7}, {%8,%9}, {%0,%1,%2,%3};"
        : "+f"(c[0]), "+f"(c[1]), "+f"(c[2]), "+f"(c[3])
        : "r"(a0), "r"(a1), "r"(a2), "r"(a3), "r"(b0), "r"(b1));
}

// pack two fp32 into f16x2 word: low16 = x0, high16 = x1
__device__ __forceinline__ uint32_t cvt_f16x2(float x1, float x0) {
    uint32_t w;
    asm("cvt.rn.f16x2.f32 %0, %1, %2;" : "=r"(w) : "f"(x1), "f"(x0));
    return w;
}

// hi/lo split of 4 floats into packed f16 words (hi = rn(x), lo = rn(x - hi))
__device__ __forceinline__ void split4(float4 v, uint32_t& h0, uint32_t& h1,
                                       uint32_t& l0, uint32_t& l1) {
    h0 = cvt_f16x2(v.y, v.x);
    h1 = cvt_f16x2(v.w, v.z);
    float hx = __half2float(__ushort_as_half((unsigned short)(h0 & 0xFFFF)));
    float hy = __half2float(__ushort_as_half((unsigned short)(h0 >> 16)));
    float hz = __half2float(__ushort_as_half((unsigned short)(h1 & 0xFFFF)));
    float hw = __half2float(__ushort_as_half((unsigned short)(h1 >> 16)));
    l0 = cvt_f16x2(v.y - hy, v.x - hx);
    l1 = cvt_f16x2(v.w - hw, v.z - hz);
}

// SMEM layout (bytes). Rows padded to 144B (64 f16 + 8 pad) => conflict-free.
#define ROWB 144
#define SM_V     0                /* 128 * 144 = 18432 */
#define SM_QS    18432            /* [128][64] f32 = 32768 */
#define SM_FUSED 51200            /* [64][128] f32 = 32768 */
#define SM_TOTAL 83968

// ---------------------------------------------------------------------------
// proj_in v4: 64-row x 32-col tiles, grid (48,16)=768 blocks, 128 threads.
// 3-term fp16 hi/lo split (fp32-accurate). Doubled grid parallelism to cover
// the serial load->sync->mma chain (proj was grid/latency-limited at 384).
// ---------------------------------------------------------------------------
#define PI_XH 0
#define PI_XL 9216
#define PI_WH 18432       /* 32 rows * 144 = 4608 */
#define PI_WL 23040
#define PI_TOTAL 27648

__global__ __launch_bounds__(128) void proj_in_v4(
    const float* __restrict__ xq, const float* __restrict__ xk,
    const float* __restrict__ xv, const float* __restrict__ W,
    const float* __restrict__ bias)
{
    const int jbase = blockIdx.x * 32;     // 0..1535
    const int rbase = blockIdx.y * 64;
    const int section = jbase >> 9;        // 0=q,1=k,2=v
    const float* __restrict__ X = (section == 0) ? xq : (section == 1) ? xk : xv;

    __shared__ char psm[PI_TOTAL];
    const uint32_t sbase = smem_u32(psm);

    const int tid = threadIdx.x;
    const int wid = tid >> 5;
    const int lane = tid & 31;

    // X loader: thread owns row=tid/2 (0..63), 32-el half
    const int xrow = tid >> 1;
    const int xth = (tid & 1) * 32;
    const float* __restrict__ xsrc = X + (size_t)(rbase + xrow) * 512 + xth;
    char* xh = psm + PI_XH + xrow * ROWB + xth * 2;
    char* xl = psm + PI_XL + xrow * ROWB + xth * 2;
    // W loader: thread owns row=tid/4 (0..31), 16-el quarter
    const int wrow = tid >> 2;
    const int wth = (tid & 3) * 16;
    const float* __restrict__ wsrc = W + (size_t)(jbase + wrow) * 512 + wth;
    char* wh = psm + PI_WH + wrow * ROWB + wth * 2;
    char* wl = psm + PI_WL + wrow * ROWB + wth * 2;

    // ldmatrix addresses (validated patterns)
    const uint32_t a_ldh = sbase + PI_XH + (wid * 16 + (lane & 15)) * ROWB +
                           ((lane >= 16) ? 16 : 0);
    const uint32_t a_ldl = a_ldh + (PI_XL - PI_XH);
    const uint32_t b_ldh = sbase + PI_WH + (lane & 7) * ROWB + ((lane >> 3) * 16);
    const uint32_t b_ldl = b_ldh + (PI_WL - PI_WH);

    float acc[4][4];
#pragma unroll
    for (int n = 0; n < 4; n++)
#pragma unroll
        for (int j = 0; j < 4; j++) acc[n][j] = 0.f;

#pragma unroll 1
    for (int kc = 0; kc < 8; kc++) {
        const int k0 = kc * 64;
        // X: 8 float4 split; W: 4 float4 split
#pragma unroll
        for (int jj = 0; jj < 32; jj += 4) {
            float4 v4 = *(const float4*)&xsrc[k0 + jj];
            uint32_t h0, h1, l0, l1;
            split4(v4, h0, h1, l0, l1);
            *(uint2*)(xh + jj * 2) = make_uint2(h0, h1);
            *(uint2*)(xl + jj * 2) = make_uint2(l0, l1);
        }
#pragma unroll
        for (int jj = 0; jj < 16; jj += 4) {
            float4 w4 = *(const float4*)&wsrc[k0 + jj];
            uint32_t h0, h1, l0, l1;
            split4(w4, h0, h1, l0, l1);
            *(uint2*)(wh + jj * 2) = make_uint2(h0, h1);
            *(uint2*)(wl + jj * 2) = make_uint2(l0, l1);
        }
        __syncthreads();

        uint32_t ah[16], al[16];
#pragma unroll
        for (int ks = 0; ks < 4; ks++) {
            ldmatrix_x4(ah[ks * 4 + 0], ah[ks * 4 + 1], ah[ks * 4 + 2],
                        ah[ks * 4 + 3], a_ldh + ks * 32);
            ldmatrix_x4(al[ks * 4 + 0], al[ks * 4 + 1], al[ks * 4 + 2],
                        al[ks * 4 + 3], a_ldl + ks * 32);
        }

#pragma unroll
        for (int nc = 0; nc < 4; nc++) {
            uint32_t bh[8], bl[8];
            ldmatrix_x4(bh[0], bh[1], bh[2], bh[3], b_ldh + nc * (8 * ROWB));
            ldmatrix_x4(bh[4], bh[5], bh[6], bh[7], b_ldh + nc * (8 * ROWB) + 64);
            ldmatrix_x4(bl[0], bl[1], bl[2], bl[3], b_ldl + nc * (8 * ROWB));
            ldmatrix_x4(bl[4], bl[5], bl[6], bl[7], b_ldl + nc * (8 * ROWB) + 64);
#pragma unroll
            for (int ks = 0; ks < 4; ks++) {
                mma_f16(acc[nc], ah[ks * 4 + 0], ah[ks * 4 + 1], ah[ks * 4 + 2],
                        ah[ks * 4 + 3], bh[ks * 2], bh[ks * 2 + 1]);
                mma_f16(acc[nc], ah[ks * 4 + 0], ah[ks * 4 + 1], ah[ks * 4 + 2],
                        ah[ks * 4 + 3], bl[ks * 2], bl[ks * 2 + 1]);
                mma_f16(acc[nc], al[ks * 4 + 0], al[ks * 4 + 1], al[ks * 4 + 2],
                        al[ks * 4 + 3], bh[ks * 2], bh[ks * 2 + 1]);
            }
        }
        __syncthreads();
    }

    // epilogue: fragment (row r0/r0+8, col jg/jg+1) per acc[nc], scatter
    const int g = lane >> 2;
    const int tig = lane & 3;
    const int r0 = rbase + wid * 16 + g;
    float* dst = (section == 0) ? g_q : (section == 1) ? g_k : g_v;

#pragma unroll
    for (int nc = 0; nc < 4; nc++) {
        const int jg = jbase + nc * 8 + 2 * tig;
        const float b0 = bias[jg], b1 = bias[jg + 1];
        float v00 = acc[nc][0] + b0, v01 = acc[nc][1] + b1;
        float v10 = acc[nc][2] + b0, v11 = acc[nc][3] + b1;
        if (section == 0) { v00 *= SCALING; v01 *= SCALING;
                            v10 *= SCALING; v11 *= SCALING; }
        const int jj = jg & 511;
        const int h = jj >> 6;
        const int dp = jj & 63;
#pragma unroll
        for (int rr = 0; rr < 2; rr++) {
            const int r = r0 + rr * 8;
            const int t = r >> 3;
            const int bb = r & 7;
            float2 val = rr ? make_float2(v10, v11) : make_float2(v00, v01);
            *(float2*)&dst[(((size_t)(bb * 8 + h)) * 128 + t) * 64 + dp] = val;
        }
    }
}

// ---------------------------------------------------------------------------
// Projection GEMM (R11 version, used for OUT-projection only): 256 threads,
// K-SPLIT across two 4-warp groups, 3-term split. Measured-good.
// ---------------------------------------------------------------------------
#define PJ_XH 0
#define PJ_XL 9216
#define PJ_WH 18432
#define PJ_WL 27648
#define PJ_BUF 36864
#define PJ_TOTAL 73728

__global__ __launch_bounds__(256) void gemm_proj_kernel(
    const float* __restrict__ W,
    const float* __restrict__ bias, float* __restrict__ outp)
{
    const int jbase = blockIdx.x * 64;
    const int rbase = blockIdx.y * 64;
    const float* __restrict__ X = g_attn2;

    extern __shared__ char psm[];
    const uint32_t sbase = smem_u32(psm);

    const int tid = threadIdx.x;
    const int wid = tid >> 5;
    const int lane = tid & 31;
    const int kgrp = wid >> 2;       // 0: chunks 0-3, 1: chunks 4-7
    const int wg = wid & 3;          // warp within group -> 16-row band

    const int ltid = tid & 127;
    const int row = ltid >> 1;
    const int th = (ltid & 1) * 32;
    const float* __restrict__ xsrc = X + (size_t)(rbase + row) * 512 + th;
    const float* __restrict__ wsrc = W + (size_t)(jbase + row) * 512 + th;
    char* mybuf = psm + kgrp * PJ_BUF;
    char* xh = mybuf + PJ_XH + row * ROWB + th * 2;
    char* xl = mybuf + PJ_XL + row * ROWB + th * 2;
    char* wh = mybuf + PJ_WH + row * ROWB + th * 2;
    char* wl = mybuf + PJ_WL + row * ROWB + th * 2;

    const uint32_t gb = sbase + kgrp * PJ_BUF;
    const uint32_t a_ldh = gb + PJ_XH + (wg * 16 + (lane & 15)) * ROWB +
                           ((lane >= 16) ? 16 : 0);
    const uint32_t a_ldl = a_ldh + (PJ_XL - PJ_XH);
    const uint32_t b_ldh = gb + PJ_WH + (lane & 7) * ROWB + ((lane >> 3) * 16);
    const uint32_t b_ldl = b_ldh + (PJ_WL - PJ_WH);

    float acc[8][4];
#pragma unroll
    for (int n = 0; n < 8; n++)
#pragma unroll
        for (int j = 0; j < 4; j++) acc[n][j] = 0.f;

#pragma unroll 1
    for (int j = 0; j < 4; j++) {
        const int k0 = (kgrp * 4 + j) * 64;
#pragma unroll
        for (int jj = 0; jj < 32; jj += 4) {
            float4 v4 = *(const float4*)&xsrc[k0 + jj];
            uint32_t h0, h1, l0, l1;
            split4(v4, h0, h1, l0, l1);
            *(uint2*)(xh + jj * 2) = make_uint2(h0, h1);
            *(uint2*)(xl + jj * 2) = make_uint2(l0, l1);
            float4 w4 = *(const float4*)&wsrc[k0 + jj];
            split4(w4, h0, h1, l0, l1);
            *(uint2*)(wh + jj * 2) = make_uint2(h0, h1);
            *(uint2*)(wl + jj * 2) = make_uint2(l0, l1);
        }
        __syncthreads();

        uint32_t ah[16], al[16];
#pragma unroll
        for (int ks = 0; ks < 4; ks++) {
            ldmatrix_x4(ah[ks * 4 + 0], ah[ks * 4 + 1], ah[ks * 4 + 2],
                        ah[ks * 4 + 3], a_ldh + ks * 32);
            ldmatrix_x4(al[ks * 4 + 0], al[ks * 4 + 1], al[ks * 4 + 2],
                        al[ks * 4 + 3], a_ldl + ks * 32);
        }

#pragma unroll
        for (int nc = 0; nc < 8; nc++) {
            uint32_t bh[8], bl[8];
            ldmatrix_x4(bh[0], bh[1], bh[2], bh[3], b_ldh + nc * (8 * ROWB));
            ldmatrix_x4(bh[4], bh[5], bh[6], bh[7], b_ldh + nc * (8 * ROWB) + 64);
            ldmatrix_x4(bl[0], bl[1], bl[2], bl[3], b_ldl + nc * (8 * ROWB));
            ldmatrix_x4(bl[4], bl[5], bl[6], bl[7], b_ldl + nc * (8 * ROWB) + 64);
#pragma unroll
            for (int ks = 0; ks < 4; ks++) {
                mma_f16(acc[nc], ah[ks * 4 + 0], ah[ks * 4 + 1], ah[ks * 4 + 2],
                        ah[ks * 4 + 3], bh[ks * 2], bh[ks * 2 + 1]);
                mma_f16(acc[nc], ah[ks * 4 + 0], ah[ks * 4 + 1], ah[ks * 4 + 2],
                        ah[ks * 4 + 3], bl[ks * 2], bl[ks * 2 + 1]);
                mma_f16(acc[nc], al[ks * 4 + 0], al[ks * 4 + 1], al[ks * 4 + 2],
                        al[ks * 4 + 3], bh[ks * 2], bh[ks * 2 + 1]);
            }
        }
        __syncthreads();
    }

    float* red = (float*)psm;
    const int rbidx = ((wg * 32 + lane) * 8) * 4;
    if (kgrp == 1) {
#pragma unroll
        for (int nc = 0; nc < 8; nc++)
            *(float4*)&red[rbidx + nc * 4] =
                make_float4(acc[nc][0], acc[nc][1], acc[nc][2], acc[nc][3]);
    }
    __syncthreads();
    if (kgrp == 0) {
        const int g = lane >> 2;
        const int tig = lane & 3;
        const int r0 = rbase + wg * 16 + g;
#pragma unroll
        for (int nc = 0; nc < 8; nc++) {
            float4 r = *(const float4*)&red[rbidx + nc * 4];
            const int jg = jbase + nc * 8 + 2 * tig;
            const float b0 = bias[jg], b1 = bias[jg + 1];
            float v00 = acc[nc][0] + r.x + b0, v01 = acc[nc][1] + r.y + b1;
            float v10 = acc[nc][2] + r.z + b0, v11 = acc[nc][3] + r.w + b1;
            *(float2*)&outp[(size_t)r0 * 512 + jg] = make_float2(v00, v01);
            *(float2*)&outp[(size_t)(r0 + 8) * 512 + jg] = make_float2(v10, v11);
        }
    }
}

// ---------------------------------------------------------------------------
// Kernel B v8: fp16 mma.sync trilinear, register-built A fragments, 16 warps,
// software-pipelined bias loads. (frozen — best measured config)
// ---------------------------------------------------------------------------
__global__ __launch_bounds__(512, 1) void tri_main_v8(const float* __restrict__ cbias)
{
    const int head  = blockIdx.x;   // 0..7
    const int ahalf = blockIdx.y;   // 0..1
    const int batch = blockIdx.z;   // 0..7
    const int i = batch * 8 + head;
    const int a0 = ahalf * 64;

    extern __shared__ char smem[];
    const uint32_t sbase = smem_u32(smem);
    float* qs    = (float*)(smem + SM_QS);
    float* fused = (float*)(smem + SM_FUSED);

    const int tid  = threadIdx.x;
    const int wid  = tid >> 5;       // 0..15
    const int lane = tid & 31;
    const int bwin = (wid & 7) * 16; // b-row window
    const int asub = (wid >> 3) * 32;

    const float* __restrict__ qi = g_q + (size_t)i * 8192;
    const float* __restrict__ ki = g_k + (size_t)i * 8192;
    const float* __restrict__ vi = g_v + (size_t)i * 8192;

    for (int idx = tid; idx < 8192; idx += 512) qs[idx] = qi[idx];

    {
        const int row = tid >> 2;
        const int tq = (tid & 3) * 16;
        char* vd = smem + SM_V + row * ROWB;
        const float* src = vi + row * 64 + tq;
#pragma unroll
        for (int j = 0; j < 16; j += 4) {
            uint32_t w0 = cvt_f16x2(src[j + 1], src[j]);
            uint32_t w1 = cvt_f16x2(src[j + 3], src[j + 2]);
            *(uint2*)(vd + (tq + j) * 2) = make_uint2(w0, w1);
        }
    }

    const int g = lane >> 2;
    const int tig = lane & 3;

    float kr0[16], kr1[16];
    {
        const float* krow0 = ki + (size_t)(bwin + g) * 64;
        const float* krow1 = krow0 + 8 * 64;
#pragma unroll
        for (int ks = 0; ks < 4; ks++) {
            int c = ks * 16 + 2 * tig;
            kr0[ks * 4 + 0] = krow0[c];     kr0[ks * 4 + 1] = krow0[c + 1];
            kr0[ks * 4 + 2] = krow0[c + 8]; kr0[ks * 4 + 3] = krow0[c + 9];
            kr1[ks * 4 + 0] = krow1[c];     kr1[ks * 4 + 1] = krow1[c + 1];
            kr1[ks * 4 + 2] = krow1[c + 8]; kr1[ks * 4 + 3] = krow1[c + 9];
        }
    }
    __syncthreads();

    const uint32_t v_ld = sbase + SM_V + (lane & 7) * ROWB + ((lane >> 3) * 16);

    const int browA = bwin + g;
    const int colbase = 2 * tig;
    const float* __restrict__ bias_b = cbias + ((size_t)batch << 21);

#pragma unroll 1
    for (int ap = 0; ap < 16; ap++) {
        const int aA = asub + 2 * ap, aB = aA + 1;

        uint32_t fa0[16], fa1[16];
        {
            const float* qA = qs + (a0 + aA) * 64;
            const float* qB = qA + 64;
#pragma unroll
            for (int ks = 0; ks < 4; ks++) {
                int c = ks * 16 + 2 * tig;
                float2 qa01 = *(const float2*)&qA[c];
                float2 qa89 = *(const float2*)&qA[c + 8];
                float2 qb01 = *(const float2*)&qB[c];
                float2 qb89 = *(const float2*)&qB[c + 8];
                fa0[ks * 4 + 0] = cvt_f16x2(kr0[ks * 4 + 1] * qa01.y, kr0[ks * 4 + 0] * qa01.x);
                fa0[ks * 4 + 1] = cvt_f16x2(kr1[ks * 4 + 1] * qa01.y, kr1[ks * 4 + 0] * qa01.x);
                fa0[ks * 4 + 2] = cvt_f16x2(kr0[ks * 4 + 3] * qa89.y, kr0[ks * 4 + 2] * qa89.x);
                fa0[ks * 4 + 3] = cvt_f16x2(kr1[ks * 4 + 3] * qa89.y, kr1[ks * 4 + 2] * qa89.x);
                fa1[ks * 4 + 0] = cvt_f16x2(kr0[ks * 4 + 1] * qb01.y, kr0[ks * 4 + 0] * qb01.x);
                fa1[ks * 4 + 1] = cvt_f16x2(kr1[ks * 4 + 1] * qb01.y, kr1[ks * 4 + 0] * qb01.x);
                fa1[ks * 4 + 2] = cvt_f16x2(kr0[ks * 4 + 3] * qb89.y, kr0[ks * 4 + 2] * qb89.x);
                fa1[ks * 4 + 3] = cvt_f16x2(kr1[ks * 4 + 3] * qb89.y, kr1[ks * 4 + 2] * qb89.x);
            }
        }

        const float* __restrict__ bpA =
            bias_b + ((size_t)(a0 + aA) << 14) + (size_t)browA * 128;
        const float* __restrict__ bpB = bpA + (1 << 14);
        float psA0 = 0.f, psA1 = 0.f, pmA0 = -1e30f, pmA1 = -1e30f;
        float psB0 = 0.f, psB1 = 0.f, pmB0 = -1e30f, pmB1 = -1e30f;

        float2 nA0 = *(const float2*)&bpA[colbase];
        float2 nA1 = *(const float2*)&bpA[8 * 128 + colbase];
        float2 nB0 = *(const float2*)&bpB[colbase];
        float2 nB1 = *(const float2*)&bpB[8 * 128 + colbase];

#pragma unroll 2
        for (int nc = 0; nc < 16; nc++) {
            float2 bA0 = nA0, bA1 = nA1, bB0 = nB0, bB1 = nB1;
            if (nc < 15) {
                const int col = (nc + 1) * 8 + colbase;
                nA0 = *(const float2*)&bpA[col];
                nA1 = *(const float2*)&bpA[8 * 128 + col];
                nB0 = *(const float2*)&bpB[col];
                nB1 = *(const float2*)&bpB[8 * 128 + col];
            }
            uint32_t b[8];
            ldmatrix_x4(b[0], b[1], b[2], b[3], v_ld + nc * (8 * ROWB));
            ldmatrix_x4(b[4], b[5], b[6], b[7], v_ld + nc * (8 * ROWB) + 64);
            float c0[4] = {0.f, 0.f, 0.f, 0.f};
            float c1[4] = {0.f, 0.f, 0.f, 0.f};
#pragma unroll
            for (int ks = 0; ks < 4; ks++) {
                mma_f16(c0, fa0[ks * 4 + 0], fa0[ks * 4 + 1], fa0[ks * 4 + 2],
                        fa0[ks * 4 + 3], b[ks * 2], b[ks * 2 + 1]);
                mma_f16(c1, fa1[ks * 4 + 0], fa1[ks * 4 + 1], fa1[ks * 4 + 2],
                        fa1[ks * 4 + 3], b[ks * 2], b[ks * 2 + 1]);
            }
            {
                float s0 = c0[0] + bA0.x, s1 = c0[1] + bA0.y;
                float s2 = c0[2] + bA1.x, s3 = c0[3] + bA1.y;
                psA0 += s0 + s1; psA1 += s2 + s3;
                pmA0 = fmaxf(pmA0, fmaxf(s0, s1));
                pmA1 = fmaxf(pmA1, fmaxf(s2, s3));
            }
            {
                float s0 = c1[0] + bB0.x, s1 = c1[1] + bB0.y;
                float s2 = c1[2] + bB1.x, s3 = c1[3] + bB1.y;
                psB0 += s0 + s1; psB1 += s2 + s3;
                pmB0 = fmaxf(pmB0, fmaxf(s0, s1));
                pmB1 = fmaxf(pmB1, fmaxf(s2, s3));
            }
        }
#pragma unroll
        for (int off = 1; off <= 2; off <<= 1) {
            psA0 += __shfl_xor_sync(0xffffffffu, psA0, off);
            psA1 += __shfl_xor_sync(0xffffffffu, psA1, off);
            psB0 += __shfl_xor_sync(0xffffffffu, psB0, off);
            psB1 += __shfl_xor_sync(0xffffffffu, psB1, off);
            pmA0 = fmaxf(pmA0, __shfl_xor_sync(0xffffffffu, pmA0, off));
            pmA1 = fmaxf(pmA1, __shfl_xor_sync(0xffffffffu, pmA1, off));
            pmB0 = fmaxf(pmB0, __shfl_xor_sync(0xffffffffu, pmB0, off));
            pmB1 = fmaxf(pmB1, __shfl_xor_sync(0xffffffffu, pmB1, off));
        }
        if (tig == 0) {
            fused[aA * 128 + browA]     = psA0 * (1.0f / 128.0f) + pmA0;
            fused[aA * 128 + browA + 8] = psA1 * (1.0f / 128.0f) + pmA1;
            fused[aB * 128 + browA]     = psB0 * (1.0f / 128.0f) + pmB0;
            fused[aB * 128 + browA + 8] = psB1 * (1.0f / 128.0f) + pmB1;
        }
    }
    __syncthreads();

    for (int a = wid; a < 64; a += 16) {
        float4 fv = *(float4*)&fused[a * 128 + lane * 4];
        float m = fmaxf(fmaxf(fv.x, fv.y), fmaxf(fv.z, fv.w));
#pragma unroll
        for (int off = 16; off >= 1; off >>= 1)
            m = fmaxf(m, __shfl_xor_sync(0xffffffffu, m, off));
        float e0 = __expf(fv.x - m), e1 = __expf(fv.y - m);
        float e2 = __expf(fv.z - m), e3 = __expf(fv.w - m);
        float s = (e0 + e1) + (e2 + e3);
#pragma unroll
        for (int off = 16; off >= 1; off >>= 1)
            s += __shfl_xor_sync(0xffffffffu, s, off);
        float inv = 1.0f / s;
        *(float4*)&fused[a * 128 + lane * 4] =
            make_float4(e0 * inv, e1 * inv, e2 * inv, e3 * inv);
    }
    __syncthreads();

    {
        int a = tid >> 3;
        int dg = (tid & 7) * 8;
        float o[8];
#pragma unroll
        for (int j = 0; j < 8; j++) o[j] = 0.f;
        const float* wrow = fused + a * 128;
#pragma unroll 4
        for (int b = 0; b < 128; b++) {
            float wb = wrow[b];
            const float* qr = qs + b * 64 + dg;
            float4 q0 = *(const float4*)&qr[0];
            float4 q1 = *(const float4*)&qr[4];
            o[0] += wb * q0.x; o[1] += wb * q0.y;
            o[2] += wb * q0.z; o[3] += wb * q0.w;
            o[4] += wb * q1.x; o[5] += wb * q1.y;
            o[6] += wb * q1.z; o[7] += wb * q1.w;
        }
        int t = a0 + a;
        float* dst = g_attn2 + ((size_t)t * 8 + batch) * 512 + head * 64 + dg;
        *(float4*)&dst[0] = make_float4(o[0], o[1], o[2], o[3]);
        *(float4*)&dst[4] = make_float4(o[4], o[5], o[6], o[7]);
    }
}

// ---------------------------------------------------------------------------
extern "C" void kernel_launch(void* const* d_in, const int* in_sizes, int n_in,
                              void* d_out, int out_size)
{
    const float* query = (const float*)d_in[0];
    const float* key   = (const float*)d_in[1];
    const float* value = (const float*)d_in[2];
    const float* cbias = (const float*)d_in[3];
    const float* ipw   = (const float*)d_in[4];
    const float* ipb   = (const float*)d_in[5];
    const float* outw  = (const float*)d_in[6];
    const float* outb  = (const float*)d_in[7];
    float* out = (float*)d_out;

    // in-projection: 32-col tiles, 768 blocks (grid-parallelism fix)
    proj_in_v4<<<dim3(48, 16), 128>>>(query, key, value, ipw, ipb);

    cudaFuncSetAttribute(tri_main_v8,
                         cudaFuncAttributeMaxDynamicSharedMemorySize, SM_TOTAL);
    tri_main_v8<<<dim3(8, 2, 8), 512, SM_TOTAL>>>(cbias);

    // out-projection: R11 K-split kernel (measured good)
    cudaFuncSetAttribute(gemm_proj_kernel,
                         cudaFuncAttributeMaxDynamicSharedMemorySize, PJ_TOTAL);
    gemm_proj_kernel<<<dim3(8, 16), 256, PJ_TOTAL>>>(outw, outb, out);
}

// round 15
// speedup vs baseline: 1.0747x; 1.0539x over previous
#include <cuda_runtime.h>
#include <cuda_fp16.h>
#include <cuda_bf16.h>
#include <math.h>
#include <stdint.h>

#define EMBED_DIM 512
#define NUM_HEADS 8
#define HEAD_DIM 64
#define T_LEN 128
#define BATCH 8
#define BH 64
#define SCALING 0.125f
#define LAMBDA 1.0f

// Scratch (allocation-free rule: __device__ globals)
__device__ float g_q[BH * T_LEN * HEAD_DIM];     // [i][t][hd], scaled
__device__ float g_k[BH * T_LEN * HEAD_DIM];
__device__ float g_v[BH * T_LEN * HEAD_DIM];
__device__ float g_attn2[T_LEN * BATCH * EMBED_DIM];  // [t][b][h*64+d]

// ---------------------------------------------------------------------------
// helpers (base ISA only: ldmatrix + mma.sync)
// ---------------------------------------------------------------------------
__device__ __forceinline__ uint32_t smem_u32(const void* p) {
    uint32_t a;
    asm("{ .reg .u64 t; cvta.to.shared.u64 t, %1; cvt.u32.u64 %0, t; }"
        : "=r"(a) : "l"(p));
    return a;
}

__device__ __forceinline__ void ldmatrix_x4(uint32_t& r0, uint32_t& r1,
                                            uint32_t& r2, uint32_t& r3,
                                            uint32_t addr) {
    asm volatile("ldmatrix.sync.aligned.m8n8.x4.shared.b16 {%0,%1,%2,%3}, [%4];"
                 : "=r"(r0), "=r"(r1), "=r"(r2), "=r"(r3) : "r"(addr));
}

__device__ __forceinline__ void mma_f16(float* c, uint32_t a0, uint32_t a1,
                                        uint32_t a2, uint32_t a3,
                                        uint32_t b0, uint32_t b1) {
    asm volatile(
        "mma.sync.aligned.m16n8k16.row.col.f32.f16.f16.f32 "
        "{%0,%1,%2,%3}, {%4,%5,%6,%7}, {%8,%9}, {%0,%1,%2,%3};"
        : "+f"(c[0]), "+f"(c[1]), "+f"(c[2]), "+f"(c[3])
        : "r"(a0), "r"(a1), "r"(a2), "r"(a3), "r"(b0), "r"(b1));
}

// pack two fp32 into f16x2 word: low16 = x0, high16 = x1
__device__ __forceinline__ uint32_t cvt_f16x2(float x1, float x0) {
    uint32_t w;
    asm("cvt.rn.f16x2.f32 %0, %1, %2;" : "=r"(w) : "f"(x1), "f"(x0));
    return w;
}

// hi/lo split of 4 floats into packed f16 words (hi = rn(x), lo = rn(x - hi))
__device__ __forceinline__ void split4(float4 v, uint32_t& h0, uint32_t& h1,
                                       uint32_t& l0, uint32_t& l1) {
    h0 = cvt_f16x2(v.y, v.x);
    h1 = cvt_f16x2(v.w, v.z);
    float hx = __half2float(__ushort_as_half((unsigned short)(h0 & 0xFFFF)));
    float hy = __half2float(__ushort_as_half((unsigned short)(h0 >> 16)));
    float hz = __half2float(__ushort_as_half((unsigned short)(h1 & 0xFFFF)));
    float hw = __half2float(__ushort_as_half((unsigned short)(h1 >> 16)));
    l0 = cvt_f16x2(v.y - hy, v.x - hx);
    l1 = cvt_f16x2(v.w - hw, v.z - hz);
}

// SMEM layout (bytes). Rows padded to 144B (64 f16 + 8 pad) => conflict-free.
#define ROWB 144
#define SM_V     0                /* 128 * 144 = 18432 */
#define SM_QS    18432            /* [128][64] f32 = 32768 */
#define SM_FUSED 51200            /* [64][128] f32 = 32768 */
#define SM_TOTAL 83968

// ---------------------------------------------------------------------------
// proj_in (R9 version — fastest measured at 48.1us): tensor cores, 3-term
// fp16 hi/lo split, 128 threads, 64x64 tile, single 36KB buffer, 8 k-chunks.
// ---------------------------------------------------------------------------
#define PJ_XH 0
#define PJ_XL 9216
#define PJ_WH 18432
#define PJ_WL 27648

__global__ __launch_bounds__(128) void proj_in_kernel(
    const float* __restrict__ xq, const float* __restrict__ xk,
    const float* __restrict__ xv, const float* __restrict__ W,
    const float* __restrict__ bias)
{
    const int jbase = blockIdx.x * 64;
    const int rbase = blockIdx.y * 64;
    const int section = jbase >> 9;
    const float* __restrict__ X = (section == 0) ? xq : (section == 1) ? xk : xv;

    __shared__ char smem[36864];
    const uint32_t sbase = smem_u32(smem);

    const int tid = threadIdx.x;
    const int wid = tid >> 5;
    const int lane = tid & 31;

    // load-phase: thread owns row=tid/2 (0..63), half th
    const int row = tid >> 1;
    const int th = (tid & 1) * 32;
    const float* __restrict__ xsrc = X + (size_t)(rbase + row) * 512 + th;
    const float* __restrict__ wsrc = W + (size_t)(jbase + row) * 512 + th;
    char* xh = smem + PJ_XH + row * ROWB + th * 2;
    char* xl = smem + PJ_XL + row * ROWB + th * 2;
    char* wh = smem + PJ_WH + row * ROWB + th * 2;
    char* wl = smem + PJ_WL + row * ROWB + th * 2;

    // ldmatrix addresses (validated patterns)
    const uint32_t a_ldh = sbase + PJ_XH + (wid * 16 + (lane & 15)) * ROWB +
                           ((lane >= 16) ? 16 : 0);
    const uint32_t a_ldl = a_ldh + (PJ_XL - PJ_XH);
    const uint32_t b_ldh = sbase + PJ_WH + (lane & 7) * ROWB + ((lane >> 3) * 16);
    const uint32_t b_ldl = b_ldh + (PJ_WL - PJ_WH);

    float acc[8][4];
#pragma unroll
    for (int n = 0; n < 8; n++)
#pragma unroll
        for (int j = 0; j < 4; j++) acc[n][j] = 0.f;

#pragma unroll 1
    for (int kc = 0; kc < 8; kc++) {
        const int k0 = kc * 64;
        // load & hi/lo split into smem
#pragma unroll
        for (int j = 0; j < 32; j += 4) {
            float4 v4 = *(const float4*)&xsrc[k0 + j];
            uint32_t h0, h1, l0, l1;
            split4(v4, h0, h1, l0, l1);
            *(uint2*)(xh + j * 2) = make_uint2(h0, h1);
            *(uint2*)(xl + j * 2) = make_uint2(l0, l1);
            float4 w4 = *(const float4*)&wsrc[k0 + j];
            split4(w4, h0, h1, l0, l1);
            *(uint2*)(wh + j * 2) = make_uint2(h0, h1);
            *(uint2*)(wl + j * 2) = make_uint2(l0, l1);
        }
        __syncthreads();

        // A fragments for this warp's 16 rows, all 4 k-steps, hi+lo
        uint32_t ah[16], al[16];
#pragma unroll
        for (int ks = 0; ks < 4; ks++) {
            ldmatrix_x4(ah[ks * 4 + 0], ah[ks * 4 + 1], ah[ks * 4 + 2],
                        ah[ks * 4 + 3], a_ldh + ks * 32);
            ldmatrix_x4(al[ks * 4 + 0], al[ks * 4 + 1], al[ks * 4 + 2],
                        al[ks * 4 + 3], a_ldl + ks * 32);
        }

#pragma unroll
        for (int nc = 0; nc < 8; nc++) {
            uint32_t bh[8], bl[8];
            ldmatrix_x4(bh[0], bh[1], bh[2], bh[3], b_ldh + nc * (8 * ROWB));
            ldmatrix_x4(bh[4], bh[5], bh[6], bh[7], b_ldh + nc * (8 * ROWB) + 64);
            ldmatrix_x4(bl[0], bl[1], bl[2], bl[3], b_ldl + nc * (8 * ROWB));
            ldmatrix_x4(bl[4], bl[5], bl[6], bl[7], b_ldl + nc * (8 * ROWB) + 64);
#pragma unroll
            for (int ks = 0; ks < 4; ks++) {
                mma_f16(acc[nc], ah[ks * 4 + 0], ah[ks * 4 + 1], ah[ks * 4 + 2],
                        ah[ks * 4 + 3], bh[ks * 2], bh[ks * 2 + 1]);
                mma_f16(acc[nc], ah[ks * 4 + 0], ah[ks * 4 + 1], ah[ks * 4 + 2],
                        ah[ks * 4 + 3], bl[ks * 2], bl[ks * 2 + 1]);
                mma_f16(acc[nc], al[ks * 4 + 0], al[ks * 4 + 1], al[ks * 4 + 2],
                        al[ks * 4 + 3], bh[ks * 2], bh[ks * 2 + 1]);
            }
        }
        __syncthreads();
    }

    // epilogue: fragment (row r0/r0+8, col jg/jg+1) per acc[nc], scatter
    const int g = lane >> 2;
    const int tig = lane & 3;
    const int r0 = rbase + wid * 16 + g;
    float* dst = (section == 0) ? g_q : (section == 1) ? g_k : g_v;

#pragma unroll
    for (int nc = 0; nc < 8; nc++) {
        const int jg = jbase + nc * 8 + 2 * tig;
        const float b0 = bias[jg], b1 = bias[jg + 1];
        float v00 = acc[nc][0] + b0, v01 = acc[nc][1] + b1;
        float v10 = acc[nc][2] + b0, v11 = acc[nc][3] + b1;
        if (section == 0) { v00 *= SCALING; v01 *= SCALING;
                            v10 *= SCALING; v11 *= SCALING; }
        const int jj = jg & 511;
        const int h = jj >> 6;
        const int dp = jj & 63;
#pragma unroll
        for (int rr = 0; rr < 2; rr++) {
            const int r = r0 + rr * 8;
            const int t = r >> 3;
            const int bb = r & 7;
            float2 val = rr ? make_float2(v10, v11) : make_float2(v00, v01);
            *(float2*)&dst[(((size_t)(bb * 8 + h)) * 128 + t) * 64 + dp] = val;
        }
    }
}

// ---------------------------------------------------------------------------
// out-projection (R11 K-split version, measured good): 256 threads, K split
// across two 4-warp groups, 3-term split, partials summed through smem.
// ---------------------------------------------------------------------------
#define PO_BUF 36864
#define PO_TOTAL 73728

__global__ __launch_bounds__(256) void proj_out_kernel(
    const float* __restrict__ W,
    const float* __restrict__ bias, float* __restrict__ outp)
{
    const int jbase = blockIdx.x * 64;
    const int rbase = blockIdx.y * 64;
    const float* __restrict__ X = g_attn2;

    extern __shared__ char psm[];
    const uint32_t sbase = smem_u32(psm);

    const int tid = threadIdx.x;
    const int wid = tid >> 5;
    const int lane = tid & 31;
    const int kgrp = wid >> 2;
    const int wg = wid & 3;

    const int ltid = tid & 127;
    const int row = ltid >> 1;
    const int th = (ltid & 1) * 32;
    const float* __restrict__ xsrc = X + (size_t)(rbase + row) * 512 + th;
    const float* __restrict__ wsrc = W + (size_t)(jbase + row) * 512 + th;
    char* mybuf = psm + kgrp * PO_BUF;
    char* xh = mybuf + PJ_XH + row * ROWB + th * 2;
    char* xl = mybuf + PJ_XL + row * ROWB + th * 2;
    char* wh = mybuf + PJ_WH + row * ROWB + th * 2;
    char* wl = mybuf + PJ_WL + row * ROWB + th * 2;

    const uint32_t gb = sbase + kgrp * PO_BUF;
    const uint32_t a_ldh = gb + PJ_XH + (wg * 16 + (lane & 15)) * ROWB +
                           ((lane >= 16) ? 16 : 0);
    const uint32_t a_ldl = a_ldh + (PJ_XL - PJ_XH);
    const uint32_t b_ldh = gb + PJ_WH + (lane & 7) * ROWB + ((lane >> 3) * 16);
    const uint32_t b_ldl = b_ldh + (PJ_WL - PJ_WH);

    float acc[8][4];
#pragma unroll
    for (int n = 0; n < 8; n++)
#pragma unroll
        for (int j = 0; j < 4; j++) acc[n][j] = 0.f;

#pragma unroll 1
    for (int j = 0; j < 4; j++) {
        const int k0 = (kgrp * 4 + j) * 64;
#pragma unroll
        for (int jj = 0; jj < 32; jj += 4) {
            float4 v4 = *(const float4*)&xsrc[k0 + jj];
            uint32_t h0, h1, l0, l1;
            split4(v4, h0, h1, l0, l1);
            *(uint2*)(xh + jj * 2) = make_uint2(h0, h1);
            *(uint2*)(xl + jj * 2) = make_uint2(l0, l1);
            float4 w4 = *(const float4*)&wsrc[k0 + jj];
            split4(w4, h0, h1, l0, l1);
            *(uint2*)(wh + jj * 2) = make_uint2(h0, h1);
            *(uint2*)(wl + jj * 2) = make_uint2(l0, l1);
        }
        __syncthreads();

        uint32_t ah[16], al[16];
#pragma unroll
        for (int ks = 0; ks < 4; ks++) {
            ldmatrix_x4(ah[ks * 4 + 0], ah[ks * 4 + 1], ah[ks * 4 + 2],
                        ah[ks * 4 + 3], a_ldh + ks * 32);
            ldmatrix_x4(al[ks * 4 + 0], al[ks * 4 + 1], al[ks * 4 + 2],
                        al[ks * 4 + 3], a_ldl + ks * 32);
        }

#pragma unroll
        for (int nc = 0; nc < 8; nc++) {
            uint32_t bh[8], bl[8];
            ldmatrix_x4(bh[0], bh[1], bh[2], bh[3], b_ldh + nc * (8 * ROWB));
            ldmatrix_x4(bh[4], bh[5], bh[6], bh[7], b_ldh + nc * (8 * ROWB) + 64);
            ldmatrix_x4(bl[0], bl[1], bl[2], bl[3], b_ldl + nc * (8 * ROWB));
            ldmatrix_x4(bl[4], bl[5], bl[6], bl[7], b_ldl + nc * (8 * ROWB) + 64);
#pragma unroll
            for (int ks = 0; ks < 4; ks++) {
                mma_f16(acc[nc], ah[ks * 4 + 0], ah[ks * 4 + 1], ah[ks * 4 + 2],
                        ah[ks * 4 + 3], bh[ks * 2], bh[ks * 2 + 1]);
                mma_f16(acc[nc], ah[ks * 4 + 0], ah[ks * 4 + 1], ah[ks * 4 + 2],
                        ah[ks * 4 + 3], bl[ks * 2], bl[ks * 2 + 1]);
                mma_f16(acc[nc], al[ks * 4 + 0], al[ks * 4 + 1], al[ks * 4 + 2],
                        al[ks * 4 + 3], bh[ks * 2], bh[ks * 2 + 1]);
            }
        }
        __syncthreads();
    }

    float* red = (float*)psm;
    const int rbidx = ((wg * 32 + lane) * 8) * 4;
    if (kgrp == 1) {
#pragma unroll
        for (int nc = 0; nc < 8; nc++)
            *(float4*)&red[rbidx + nc * 4] =
                make_float4(acc[nc][0], acc[nc][1], acc[nc][2], acc[nc][3]);
    }
    __syncthreads();
    if (kgrp == 0) {
        const int g = lane >> 2;
        const int tig = lane & 3;
        const int r0 = rbase + wg * 16 + g;
#pragma unroll
        for (int nc = 0; nc < 8; nc++) {
            float4 r = *(const float4*)&red[rbidx + nc * 4];
            const int jg = jbase + nc * 8 + 2 * tig;
            const float b0 = bias[jg], b1 = bias[jg + 1];
            float v00 = acc[nc][0] + r.x + b0, v01 = acc[nc][1] + r.y + b1;
            float v10 = acc[nc][2] + r.z + b0, v11 = acc[nc][3] + r.w + b1;
            *(float2*)&outp[(size_t)r0 * 512 + jg] = make_float2(v00, v01);
            *(float2*)&outp[(size_t)(r0 + 8) * 512 + jg] = make_float2(v10, v11);
        }
    }
}

// ---------------------------------------------------------------------------
// Kernel B v8: fp16 mma.sync trilinear, register-built A fragments, 16 warps,
// software-pipelined bias loads. (frozen — best measured config)
// ---------------------------------------------------------------------------
__global__ __launch_bounds__(512, 1) void tri_main_v8(const float* __restrict__ cbias)
{
    const int head  = blockIdx.x;   // 0..7
    const int ahalf = blockIdx.y;   // 0..1
    const int batch = blockIdx.z;   // 0..7
    const int i = batch * 8 + head;
    const int a0 = ahalf * 64;

    extern __shared__ char smem[];
    const uint32_t sbase = smem_u32(smem);
    float* qs    = (float*)(smem + SM_QS);
    float* fused = (float*)(smem + SM_FUSED);

    const int tid  = threadIdx.x;
    const int wid  = tid >> 5;       // 0..15
    const int lane = tid & 31;
    const int bwin = (wid & 7) * 16; // b-row window
    const int asub = (wid >> 3) * 32;

    const float* __restrict__ qi = g_q + (size_t)i * 8192;
    const float* __restrict__ ki = g_k + (size_t)i * 8192;
    const float* __restrict__ vi = g_v + (size_t)i * 8192;

    for (int idx = tid; idx < 8192; idx += 512) qs[idx] = qi[idx];

    {
        const int row = tid >> 2;
        const int tq = (tid & 3) * 16;
        char* vd = smem + SM_V + row * ROWB;
        const float* src = vi + row * 64 + tq;
#pragma unroll
        for (int j = 0; j < 16; j += 4) {
            uint32_t w0 = cvt_f16x2(src[j + 1], src[j]);
            uint32_t w1 = cvt_f16x2(src[j + 3], src[j + 2]);
            *(uint2*)(vd + (tq + j) * 2) = make_uint2(w0, w1);
        }
    }

    const int g = lane >> 2;
    const int tig = lane & 3;

    float kr0[16], kr1[16];
    {
        const float* krow0 = ki + (size_t)(bwin + g) * 64;
        const float* krow1 = krow0 + 8 * 64;
#pragma unroll
        for (int ks = 0; ks < 4; ks++) {
            int c = ks * 16 + 2 * tig;
            kr0[ks * 4 + 0] = krow0[c];     kr0[ks * 4 + 1] = krow0[c + 1];
            kr0[ks * 4 + 2] = krow0[c + 8]; kr0[ks * 4 + 3] = krow0[c + 9];
            kr1[ks * 4 + 0] = krow1[c];     kr1[ks * 4 + 1] = krow1[c + 1];
            kr1[ks * 4 + 2] = krow1[c + 8]; kr1[ks * 4 + 3] = krow1[c + 9];
        }
    }
    __syncthreads();

    const uint32_t v_ld = sbase + SM_V + (lane & 7) * ROWB + ((lane >> 3) * 16);

    const int browA = bwin + g;
    const int colbase = 2 * tig;
    const float* __restrict__ bias_b = cbias + ((size_t)batch << 21);

#pragma unroll 1
    for (int ap = 0; ap < 16; ap++) {
        const int aA = asub + 2 * ap, aB = aA + 1;

        uint32_t fa0[16], fa1[16];
        {
            const float* qA = qs + (a0 + aA) * 64;
            const float* qB = qA + 64;
#pragma unroll
            for (int ks = 0; ks < 4; ks++) {
                int c = ks * 16 + 2 * tig;
                float2 qa01 = *(const float2*)&qA[c];
                float2 qa89 = *(const float2*)&qA[c + 8];
                float2 qb01 = *(const float2*)&qB[c];
                float2 qb89 = *(const float2*)&qB[c + 8];
                fa0[ks * 4 + 0] = cvt_f16x2(kr0[ks * 4 + 1] * qa01.y, kr0[ks * 4 + 0] * qa01.x);
                fa0[ks * 4 + 1] = cvt_f16x2(kr1[ks * 4 + 1] * qa01.y, kr1[ks * 4 + 0] * qa01.x);
                fa0[ks * 4 + 2] = cvt_f16x2(kr0[ks * 4 + 3] * qa89.y, kr0[ks * 4 + 2] * qa89.x);
                fa0[ks * 4 + 3] = cvt_f16x2(kr1[ks * 4 + 3] * qa89.y, kr1[ks * 4 + 2] * qa89.x);
                fa1[ks * 4 + 0] = cvt_f16x2(kr0[ks * 4 + 1] * qb01.y, kr0[ks * 4 + 0] * qb01.x);
                fa1[ks * 4 + 1] = cvt_f16x2(kr1[ks * 4 + 1] * qb01.y, kr1[ks * 4 + 0] * qb01.x);
                fa1[ks * 4 + 2] = cvt_f16x2(kr0[ks * 4 + 3] * qb89.y, kr0[ks * 4 + 2] * qb89.x);
                fa1[ks * 4 + 3] = cvt_f16x2(kr1[ks * 4 + 3] * qb89.y, kr1[ks * 4 + 2] * qb89.x);
            }
        }

        const float* __restrict__ bpA =
            bias_b + ((size_t)(a0 + aA) << 14) + (size_t)browA * 128;
        const float* __restrict__ bpB = bpA + (1 << 14);
        float psA0 = 0.f, psA1 = 0.f, pmA0 = -1e30f, pmA1 = -1e30f;
        float psB0 = 0.f, psB1 = 0.f, pmB0 = -1e30f, pmB1 = -1e30f;

        float2 nA0 = *(const float2*)&bpA[colbase];
        float2 nA1 = *(const float2*)&bpA[8 * 128 + colbase];
        float2 nB0 = *(const float2*)&bpB[colbase];
        float2 nB1 = *(const float2*)&bpB[8 * 128 + colbase];

#pragma unroll 2
        for (int nc = 0; nc < 16; nc++) {
            float2 bA0 = nA0, bA1 = nA1, bB0 = nB0, bB1 = nB1;
            if (nc < 15) {
                const int col = (nc + 1) * 8 + colbase;
                nA0 = *(const float2*)&bpA[col];
                nA1 = *(const float2*)&bpA[8 * 128 + col];
                nB0 = *(const float2*)&bpB[col];
                nB1 = *(const float2*)&bpB[8 * 128 + col];
            }
            uint32_t b[8];
            ldmatrix_x4(b[0], b[1], b[2], b[3], v_ld + nc * (8 * ROWB));
            ldmatrix_x4(b[4], b[5], b[6], b[7], v_ld + nc * (8 * ROWB) + 64);
            float c0[4] = {0.f, 0.f, 0.f, 0.f};
            float c1[4] = {0.f, 0.f, 0.f, 0.f};
#pragma unroll
            for (int ks = 0; ks < 4; ks++) {
                mma_f16(c0, fa0[ks * 4 + 0], fa0[ks * 4 + 1], fa0[ks * 4 + 2],
                        fa0[ks * 4 + 3], b[ks * 2], b[ks * 2 + 1]);
                mma_f16(c1, fa1[ks * 4 + 0], fa1[ks * 4 + 1], fa1[ks * 4 + 2],
                        fa1[ks * 4 + 3], b[ks * 2], b[ks * 2 + 1]);
            }
            {
                float s0 = c0[0] + bA0.x, s1 = c0[1] + bA0.y;
                float s2 = c0[2] + bA1.x, s3 = c0[3] + bA1.y;
                psA0 += s0 + s1; psA1 += s2 + s3;
                pmA0 = fmaxf(pmA0, fmaxf(s0, s1));
                pmA1 = fmaxf(pmA1, fmaxf(s2, s3));
            }
            {
                float s0 = c1[0] + bB0.x, s1 = c1[1] + bB0.y;
                float s2 = c1[2] + bB1.x, s3 = c1[3] + bB1.y;
                psB0 += s0 + s1; psB1 += s2 + s3;
                pmB0 = fmaxf(pmB0, fmaxf(s0, s1));
                pmB1 = fmaxf(pmB1, fmaxf(s2, s3));
            }
        }
#pragma unroll
        for (int off = 1; off <= 2; off <<= 1) {
            psA0 += __shfl_xor_sync(0xffffffffu, psA0, off);
            psA1 += __shfl_xor_sync(0xffffffffu, psA1, off);
            psB0 += __shfl_xor_sync(0xffffffffu, psB0, off);
            psB1 += __shfl_xor_sync(0xffffffffu, psB1, off);
            pmA0 = fmaxf(pmA0, __shfl_xor_sync(0xffffffffu, pmA0, off));
            pmA1 = fmaxf(pmA1, __shfl_xor_sync(0xffffffffu, pmA1, off));
            pmB0 = fmaxf(pmB0, __shfl_xor_sync(0xffffffffu, pmB0, off));
            pmB1 = fmaxf(pmB1, __shfl_xor_sync(0xffffffffu, pmB1, off));
        }
        if (tig == 0) {
            fused[aA * 128 + browA]     = psA0 * (1.0f / 128.0f) + pmA0;
            fused[aA * 128 + browA + 8] = psA1 * (1.0f / 128.0f) + pmA1;
            fused[aB * 128 + browA]     = psB0 * (1.0f / 128.0f) + pmB0;
            fused[aB * 128 + browA + 8] = psB1 * (1.0f / 128.0f) + pmB1;
        }
    }
    __syncthreads();

    for (int a = wid; a < 64; a += 16) {
        float4 fv = *(float4*)&fused[a * 128 + lane * 4];
        float m = fmaxf(fmaxf(fv.x, fv.y), fmaxf(fv.z, fv.w));
#pragma unroll
        for (int off = 16; off >= 1; off >>= 1)
            m = fmaxf(m, __shfl_xor_sync(0xffffffffu, m, off));
        float e0 = __expf(fv.x - m), e1 = __expf(fv.y - m);
        float e2 = __expf(fv.z - m), e3 = __expf(fv.w - m);
        float s = (e0 + e1) + (e2 + e3);
#pragma unroll
        for (int off = 16; off >= 1; off >>= 1)
            s += __shfl_xor_sync(0xffffffffu, s, off);
        float inv = 1.0f / s;
        *(float4*)&fused[a * 128 + lane * 4] =
            make_float4(e0 * inv, e1 * inv, e2 * inv, e3 * inv);
    }
    __syncthreads();

    {
        int a = tid >> 3;
        int dg = (tid & 7) * 8;
        float o[8];
#pragma unroll
        for (int j = 0; j < 8; j++) o[j] = 0.f;
        const float* wrow = fused + a * 128;
#pragma unroll 4
        for (int b = 0; b < 128; b++) {
            float wb = wrow[b];
            const float* qr = qs + b * 64 + dg;
            float4 q0 = *(const float4*)&qr[0];
            float4 q1 = *(const float4*)&qr[4];
            o[0] += wb * q0.x; o[1] += wb * q0.y;
            o[2] += wb * q0.z; o[3] += wb * q0.w;
            o[4] += wb * q1.x; o[5] += wb * q1.y;
            o[6] += wb * q1.z; o[7] += wb * q1.w;
        }
        int t = a0 + a;
        float* dst = g_attn2 + ((size_t)t * 8 + batch) * 512 + head * 64 + dg;
        *(float4*)&dst[0] = make_float4(o[0], o[1], o[2], o[3]);
        *(float4*)&dst[4] = make_float4(o[4], o[5], o[6], o[7]);
    }
}

// ---------------------------------------------------------------------------
extern "C" void kernel_launch(void* const* d_in, const int* in_sizes, int n_in,
                              void* d_out, int out_size)
{
    const float* query = (const float*)d_in[0];
    const float* key   = (const float*)d_in[1];
    const float* value = (const float*)d_in[2];
    const float* cbias = (const float*)d_in[3];
    const float* ipw   = (const float*)d_in[4];
    const float* ipb   = (const float*)d_in[5];
    const float* outw  = (const float*)d_in[6];
    const float* outb  = (const float*)d_in[7];
    float* out = (float*)d_out;

    // in-projection: R9 version (fastest measured, 48.1us)
    proj_in_kernel<<<dim3(24, 16), 128>>>(query, key, value, ipw, ipb);

    cudaFuncSetAttribute(tri_main_v8,
                         cudaFuncAttributeMaxDynamicSharedMemorySize, SM_TOTAL);
    tri_main_v8<<<dim3(8, 2, 8), 512, SM_TOTAL>>>(cbias);

    // out-projection: R11 K-split version (measured good)
    cudaFuncSetAttribute(proj_out_kernel,
                         cudaFuncAttributeMaxDynamicSharedMemorySize, PO_TOTAL);
    proj_out_kernel<<<dim3(8, 16), 256, PO_TOTAL>>>(outw, outb, out);
}

// round 16
// speedup vs baseline: 1.0859x; 1.0104x over previous
#include <cuda_runtime.h>
#include <cuda_fp16.h>
#include <cuda_bf16.h>
#include <math.h>
#include <stdint.h>

#define EMBED_DIM 512
#define NUM_HEADS 8
#define HEAD_DIM 64
#define T_LEN 128
#define BATCH 8
#define BH 64
#define SCALING 0.125f
#define LAMBDA 1.0f

// Scratch (allocation-free rule: __device__ globals)
__device__ float g_q[BH * T_LEN * HEAD_DIM];     // [i][t][hd], scaled
__device__ float g_k[BH * T_LEN * HEAD_DIM];
__device__ float g_v[BH * T_LEN * HEAD_DIM];
__device__ float g_attn2[T_LEN * BATCH * EMBED_DIM];  // [t][b][h*64+d]

// ---------------------------------------------------------------------------
// helpers (base ISA only: ldmatrix + mma.sync)
// ---------------------------------------------------------------------------
__device__ __forceinline__ uint32_t smem_u32(const void* p) {
    uint32_t a;
    asm("{ .reg .u64 t; cvta.to.shared.u64 t, %1; cvt.u32.u64 %0, t; }"
        : "=r"(a) : "l"(p));
    return a;
}

__device__ __forceinline__ void ldmatrix_x4(uint32_t& r0, uint32_t& r1,
                                            uint32_t& r2, uint32_t& r3,
                                            uint32_t addr) {
    asm volatile("ldmatrix.sync.aligned.m8n8.x4.shared.b16 {%0,%1,%2,%3}, [%4];"
                 : "=r"(r0), "=r"(r1), "=r"(r2), "=r"(r3) : "r"(addr));
}

__device__ __forceinline__ void mma_f16(float* c, uint32_t a0, uint32_t a1,
                                        uint32_t a2, uint32_t a3,
                                        uint32_t b0, uint32_t b1) {
    asm volatile(
        "mma.sync.aligned.m16n8k16.row.col.f32.f16.f16.f32 "
        "{%0,%1,%2,%3}, {%4,%5,%6,%7}, {%8,%9}, {%0,%1,%2,%3};"
        : "+f"(c[0]), "+f"(c[1]), "+f"(c[2]), "+f"(c[3])
        : "r"(a0), "r"(a1), "r"(a2), "r"(a3), "r"(b0), "r"(b1));
}

// pack two fp32 into f16x2 word: low16 = x0, high16 = x1
__device__ __forceinline__ uint32_t cvt_f16x2(float x1, float x0) {
    uint32_t w;
    asm("cvt.rn.f16x2.f32 %0, %1, %2;" : "=r"(w) : "f"(x1), "f"(x0));
    return w;
}

// hi/lo split of 4 floats into packed f16 words (hi = rn(x), lo = rn(x - hi))
__device__ __forceinline__ void split4(float4 v, uint32_t& h0, uint32_t& h1,
                                       uint32_t& l0, uint32_t& l1) {
    h0 = cvt_f16x2(v.y, v.x);
    h1 = cvt_f16x2(v.w, v.z);
    float hx = __half2float(__ushort_as_half((unsigned short)(h0 & 0xFFFF)));
    float hy = __half2float(__ushort_as_half((unsigned short)(h0 >> 16)));
    float hz = __half2float(__ushort_as_half((unsigned short)(h1 & 0xFFFF)));
    float hw = __half2float(__ushort_as_half((unsigned short)(h1 >> 16)));
    l0 = cvt_f16x2(v.y - hy, v.x - hx);
    l1 = cvt_f16x2(v.w - hw, v.z - hz);
}

// SMEM layout (bytes). Rows padded to 144B (64 f16 + 8 pad) => conflict-free.
#define ROWB 144
#define SM_V     0                /* 128 * 144 = 18432 */
#define SM_QS    18432            /* [128][64] f32 = 32768 */
#define SM_FUSED 51200            /* [64][128] f32 = 32768 */
#define SM_TOTAL 83968

// ---------------------------------------------------------------------------
// proj_in (R9 version — fastest measured at ~47us): tensor cores, 3-term
// fp16 hi/lo split, 128 threads, 64x64 tile, single 36KB buffer, 8 k-chunks.
// ---------------------------------------------------------------------------
#define PJ_XH 0
#define PJ_XL 9216
#define PJ_WH 18432
#define PJ_WL 27648

__global__ __launch_bounds__(128) void proj_in_kernel(
    const float* __restrict__ xq, const float* __restrict__ xk,
    const float* __restrict__ xv, const float* __restrict__ W,
    const float* __restrict__ bias)
{
    const int jbase = blockIdx.x * 64;
    const int rbase = blockIdx.y * 64;
    const int section = jbase >> 9;
    const float* __restrict__ X = (section == 0) ? xq : (section == 1) ? xk : xv;

    __shared__ char smem[36864];
    const uint32_t sbase = smem_u32(smem);

    const int tid = threadIdx.x;
    const int wid = tid >> 5;
    const int lane = tid & 31;

    const int row = tid >> 1;
    const int th = (tid & 1) * 32;
    const float* __restrict__ xsrc = X + (size_t)(rbase + row) * 512 + th;
    const float* __restrict__ wsrc = W + (size_t)(jbase + row) * 512 + th;
    char* xh = smem + PJ_XH + row * ROWB + th * 2;
    char* xl = smem + PJ_XL + row * ROWB + th * 2;
    char* wh = smem + PJ_WH + row * ROWB + th * 2;
    char* wl = smem + PJ_WL + row * ROWB + th * 2;

    const uint32_t a_ldh = sbase + PJ_XH + (wid * 16 + (lane & 15)) * ROWB +
                           ((lane >= 16) ? 16 : 0);
    const uint32_t a_ldl = a_ldh + (PJ_XL - PJ_XH);
    const uint32_t b_ldh = sbase + PJ_WH + (lane & 7) * ROWB + ((lane >> 3) * 16);
    const uint32_t b_ldl = b_ldh + (PJ_WL - PJ_WH);

    float acc[8][4];
#pragma unroll
    for (int n = 0; n < 8; n++)
#pragma unroll
        for (int j = 0; j < 4; j++) acc[n][j] = 0.f;

#pragma unroll 1
    for (int kc = 0; kc < 8; kc++) {
        const int k0 = kc * 64;
#pragma unroll
        for (int j = 0; j < 32; j += 4) {
            float4 v4 = *(const float4*)&xsrc[k0 + j];
            uint32_t h0, h1, l0, l1;
            split4(v4, h0, h1, l0, l1);
            *(uint2*)(xh + j * 2) = make_uint2(h0, h1);
            *(uint2*)(xl + j * 2) = make_uint2(l0, l1);
            float4 w4 = *(const float4*)&wsrc[k0 + j];
            split4(w4, h0, h1, l0, l1);
            *(uint2*)(wh + j * 2) = make_uint2(h0, h1);
            *(uint2*)(wl + j * 2) = make_uint2(l0, l1);
        }
        __syncthreads();

        uint32_t ah[16], al[16];
#pragma unroll
        for (int ks = 0; ks < 4; ks++) {
            ldmatrix_x4(ah[ks * 4 + 0], ah[ks * 4 + 1], ah[ks * 4 + 2],
                        ah[ks * 4 + 3], a_ldh + ks * 32);
            ldmatrix_x4(al[ks * 4 + 0], al[ks * 4 + 1], al[ks * 4 + 2],
                        al[ks * 4 + 3], a_ldl + ks * 32);
        }

#pragma unroll
        for (int nc = 0; nc < 8; nc++) {
            uint32_t bh[8], bl[8];
            ldmatrix_x4(bh[0], bh[1], bh[2], bh[3], b_ldh + nc * (8 * ROWB));
            ldmatrix_x4(bh[4], bh[5], bh[6], bh[7], b_ldh + nc * (8 * ROWB) + 64);
            ldmatrix_x4(bl[0], bl[1], bl[2], bl[3], b_ldl + nc * (8 * ROWB));
            ldmatrix_x4(bl[4], bl[5], bl[6], bl[7], b_ldl + nc * (8 * ROWB) + 64);
#pragma unroll
            for (int ks = 0; ks < 4; ks++) {
                mma_f16(acc[nc], ah[ks * 4 + 0], ah[ks * 4 + 1], ah[ks * 4 + 2],
                        ah[ks * 4 + 3], bh[ks * 2], bh[ks * 2 + 1]);
                mma_f16(acc[nc], ah[ks * 4 + 0], ah[ks * 4 + 1], ah[ks * 4 + 2],
                        ah[ks * 4 + 3], bl[ks * 2], bl[ks * 2 + 1]);
                mma_f16(acc[nc], al[ks * 4 + 0], al[ks * 4 + 1], al[ks * 4 + 2],
                        al[ks * 4 + 3], bh[ks * 2], bh[ks * 2 + 1]);
            }
        }
        __syncthreads();
    }

    const int g = lane >> 2;
    const int tig = lane & 3;
    const int r0 = rbase + wid * 16 + g;
    float* dst = (section == 0) ? g_q : (section == 1) ? g_k : g_v;

#pragma unroll
    for (int nc = 0; nc < 8; nc++) {
        const int jg = jbase + nc * 8 + 2 * tig;
        const float b0 = bias[jg], b1 = bias[jg + 1];
        float v00 = acc[nc][0] + b0, v01 = acc[nc][1] + b1;
        float v10 = acc[nc][2] + b0, v11 = acc[nc][3] + b1;
        if (section == 0) { v00 *= SCALING; v01 *= SCALING;
                            v10 *= SCALING; v11 *= SCALING; }
        const int jj = jg & 511;
        const int h = jj >> 6;
        const int dp = jj & 63;
#pragma unroll
        for (int rr = 0; rr < 2; rr++) {
            const int r = r0 + rr * 8;
            const int t = r >> 3;
            const int bb = r & 7;
            float2 val = rr ? make_float2(v10, v11) : make_float2(v00, v01);
            *(float2*)&dst[(((size_t)(bb * 8 + h)) * 128 + t) * 64 + dp] = val;
        }
    }
}

// ---------------------------------------------------------------------------
// out-projection (R11 K-split version, measured good)
// ---------------------------------------------------------------------------
#define PO_BUF 36864
#define PO_TOTAL 73728

__global__ __launch_bounds__(256) void proj_out_kernel(
    const float* __restrict__ W,
    const float* __restrict__ bias, float* __restrict__ outp)
{
    const int jbase = blockIdx.x * 64;
    const int rbase = blockIdx.y * 64;
    const float* __restrict__ X = g_attn2;

    extern __shared__ char psm[];
    const uint32_t sbase = smem_u32(psm);

    const int tid = threadIdx.x;
    const int wid = tid >> 5;
    const int lane = tid & 31;
    const int kgrp = wid >> 2;
    const int wg = wid & 3;

    const int ltid = tid & 127;
    const int row = ltid >> 1;
    const int th = (ltid & 1) * 32;
    const float* __restrict__ xsrc = X + (size_t)(rbase + row) * 512 + th;
    const float* __restrict__ wsrc = W + (size_t)(jbase + row) * 512 + th;
    char* mybuf = psm + kgrp * PO_BUF;
    char* xh = mybuf + PJ_XH + row * ROWB + th * 2;
    char* xl = mybuf + PJ_XL + row * ROWB + th * 2;
    char* wh = mybuf + PJ_WH + row * ROWB + th * 2;
    char* wl = mybuf + PJ_WL + row * ROWB + th * 2;

    const uint32_t gb = sbase + kgrp * PO_BUF;
    const uint32_t a_ldh = gb + PJ_XH + (wg * 16 + (lane & 15)) * ROWB +
                           ((lane >= 16) ? 16 : 0);
    const uint32_t a_ldl = a_ldh + (PJ_XL - PJ_XH);
    const uint32_t b_ldh = gb + PJ_WH + (lane & 7) * ROWB + ((lane >> 3) * 16);
    const uint32_t b_ldl = b_ldh + (PJ_WL - PJ_WH);

    float acc[8][4];
#pragma unroll
    for (int n = 0; n < 8; n++)
#pragma unroll
        for (int j = 0; j < 4; j++) acc[n][j] = 0.f;

#pragma unroll 1
    for (int j = 0; j < 4; j++) {
        const int k0 = (kgrp * 4 + j) * 64;
#pragma unroll
        for (int jj = 0; jj < 32; jj += 4) {
            float4 v4 = *(const float4*)&xsrc[k0 + jj];
            uint32_t h0, h1, l0, l1;
            split4(v4, h0, h1, l0, l1);
            *(uint2*)(xh + jj * 2) = make_uint2(h0, h1);
            *(uint2*)(xl + jj * 2) = make_uint2(l0, l1);
            float4 w4 = *(const float4*)&wsrc[k0 + jj];
            split4(w4, h0, h1, l0, l1);
            *(uint2*)(wh + jj * 2) = make_uint2(h0, h1);
            *(uint2*)(wl + jj * 2) = make_uint2(l0, l1);
        }
        __syncthreads();

        uint32_t ah[16], al[16];
#pragma unroll
        for (int ks = 0; ks < 4; ks++) {
            ldmatrix_x4(ah[ks * 4 + 0], ah[ks * 4 + 1], ah[ks * 4 + 2],
                        ah[ks * 4 + 3], a_ldh + ks * 32);
            ldmatrix_x4(al[ks * 4 + 0], al[ks * 4 + 1], al[ks * 4 + 2],
                        al[ks * 4 + 3], a_ldl + ks * 32);
        }

#pragma unroll
        for (int nc = 0; nc < 8; nc++) {
            uint32_t bh[8], bl[8];
            ldmatrix_x4(bh[0], bh[1], bh[2], bh[3], b_ldh + nc * (8 * ROWB));
            ldmatrix_x4(bh[4], bh[5], bh[6], bh[7], b_ldh + nc * (8 * ROWB) + 64);
            ldmatrix_x4(bl[0], bl[1], bl[2], bl[3], b_ldl + nc * (8 * ROWB));
            ldmatrix_x4(bl[4], bl[5], bl[6], bl[7], b_ldl + nc * (8 * ROWB) + 64);
#pragma unroll
            for (int ks = 0; ks < 4; ks++) {
                mma_f16(acc[nc], ah[ks * 4 + 0], ah[ks * 4 + 1], ah[ks * 4 + 2],
                        ah[ks * 4 + 3], bh[ks * 2], bh[ks * 2 + 1]);
                mma_f16(acc[nc], ah[ks * 4 + 0], ah[ks * 4 + 1], ah[ks * 4 + 2],
                        ah[ks * 4 + 3], bl[ks * 2], bl[ks * 2 + 1]);
                mma_f16(acc[nc], al[ks * 4 + 0], al[ks * 4 + 1], al[ks * 4 + 2],
                        al[ks * 4 + 3], bh[ks * 2], bh[ks * 2 + 1]);
            }
        }
        __syncthreads();
    }

    float* red = (float*)psm;
    const int rbidx = ((wg * 32 + lane) * 8) * 4;
    if (kgrp == 1) {
#pragma unroll
        for (int nc = 0; nc < 8; nc++)
            *(float4*)&red[rbidx + nc * 4] =
                make_float4(acc[nc][0], acc[nc][1], acc[nc][2], acc[nc][3]);
    }
    __syncthreads();
    if (kgrp == 0) {
        const int g = lane >> 2;
        const int tig = lane & 3;
        const int r0 = rbase + wg * 16 + g;
#pragma unroll
        for (int nc = 0; nc < 8; nc++) {
            float4 r = *(const float4*)&red[rbidx + nc * 4];
            const int jg = jbase + nc * 8 + 2 * tig;
            const float b0 = bias[jg], b1 = bias[jg + 1];
            float v00 = acc[nc][0] + r.x + b0, v01 = acc[nc][1] + r.y + b1;
            float v10 = acc[nc][2] + r.z + b0, v11 = acc[nc][3] + r.w + b1;
            *(float2*)&outp[(size_t)r0 * 512 + jg] = make_float2(v00, v01);
            *(float2*)&outp[(size_t)(r0 + 8) * 512 + jg] = make_float2(v10, v11);
        }
    }
}

// ---------------------------------------------------------------------------
// Kernel B v10: v8 with SPLIT ACCUMULATOR CHAINS — 4 independent depth-2 mma
// chains per nc (c0a/c0b/c1a/c1b) instead of 2 depth-4 chains. Pure ILP.
// ---------------------------------------------------------------------------
__global__ __launch_bounds__(512, 1) void tri_main_v10(const float* __restrict__ cbias)
{
    const int head  = blockIdx.x;   // 0..7
    const int ahalf = blockIdx.y;   // 0..1
    const int batch = blockIdx.z;   // 0..7
    const int i = batch * 8 + head;
    const int a0 = ahalf * 64;

    extern __shared__ char smem[];
    const uint32_t sbase = smem_u32(smem);
    float* qs    = (float*)(smem + SM_QS);
    float* fused = (float*)(smem + SM_FUSED);

    const int tid  = threadIdx.x;
    const int wid  = tid >> 5;       // 0..15
    const int lane = tid & 31;
    const int bwin = (wid & 7) * 16; // b-row window
    const int asub = (wid >> 3) * 32;

    const float* __restrict__ qi = g_q + (size_t)i * 8192;
    const float* __restrict__ ki = g_k + (size_t)i * 8192;
    const float* __restrict__ vi = g_v + (size_t)i * 8192;

    for (int idx = tid; idx < 8192; idx += 512) qs[idx] = qi[idx];

    {
        const int row = tid >> 2;
        const int tq = (tid & 3) * 16;
        char* vd = smem + SM_V + row * ROWB;
        const float* src = vi + row * 64 + tq;
#pragma unroll
        for (int j = 0; j < 16; j += 4) {
            uint32_t w0 = cvt_f16x2(src[j + 1], src[j]);
            uint32_t w1 = cvt_f16x2(src[j + 3], src[j + 2]);
            *(uint2*)(vd + (tq + j) * 2) = make_uint2(w0, w1);
        }
    }

    const int g = lane >> 2;
    const int tig = lane & 3;

    float kr0[16], kr1[16];
    {
        const float* krow0 = ki + (size_t)(bwin + g) * 64;
        const float* krow1 = krow0 + 8 * 64;
#pragma unroll
        for (int ks = 0; ks < 4; ks++) {
            int c = ks * 16 + 2 * tig;
            kr0[ks * 4 + 0] = krow0[c];     kr0[ks * 4 + 1] = krow0[c + 1];
            kr0[ks * 4 + 2] = krow0[c + 8]; kr0[ks * 4 + 3] = krow0[c + 9];
            kr1[ks * 4 + 0] = krow1[c];     kr1[ks * 4 + 1] = krow1[c + 1];
            kr1[ks * 4 + 2] = krow1[c + 8]; kr1[ks * 4 + 3] = krow1[c + 9];
        }
    }
    __syncthreads();

    const uint32_t v_ld = sbase + SM_V + (lane & 7) * ROWB + ((lane >> 3) * 16);

    const int browA = bwin + g;
    const int colbase = 2 * tig;
    const float* __restrict__ bias_b = cbias + ((size_t)batch << 21);

#pragma unroll 1
    for (int ap = 0; ap < 16; ap++) {
        const int aA = asub + 2 * ap, aB = aA + 1;

        uint32_t fa0[16], fa1[16];
        {
            const float* qA = qs + (a0 + aA) * 64;
            const float* qB = qA + 64;
#pragma unroll
            for (int ks = 0; ks < 4; ks++) {
                int c = ks * 16 + 2 * tig;
                float2 qa01 = *(const float2*)&qA[c];
                float2 qa89 = *(const float2*)&qA[c + 8];
                float2 qb01 = *(const float2*)&qB[c];
                float2 qb89 = *(const float2*)&qB[c + 8];
                fa0[ks * 4 + 0] = cvt_f16x2(kr0[ks * 4 + 1] * qa01.y, kr0[ks * 4 + 0] * qa01.x);
                fa0[ks * 4 + 1] = cvt_f16x2(kr1[ks * 4 + 1] * qa01.y, kr1[ks * 4 + 0] * qa01.x);
                fa0[ks * 4 + 2] = cvt_f16x2(kr0[ks * 4 + 3] * qa89.y, kr0[ks * 4 + 2] * qa89.x);
                fa0[ks * 4 + 3] = cvt_f16x2(kr1[ks * 4 + 3] * qa89.y, kr1[ks * 4 + 2] * qa89.x);
                fa1[ks * 4 + 0] = cvt_f16x2(kr0[ks * 4 + 1] * qb01.y, kr0[ks * 4 + 0] * qb01.x);
                fa1[ks * 4 + 1] = cvt_f16x2(kr1[ks * 4 + 1] * qb01.y, kr1[ks * 4 + 0] * qb01.x);
                fa1[ks * 4 + 2] = cvt_f16x2(kr0[ks * 4 + 3] * qb89.y, kr0[ks * 4 + 2] * qb89.x);
                fa1[ks * 4 + 3] = cvt_f16x2(kr1[ks * 4 + 3] * qb89.y, kr1[ks * 4 + 2] * qb89.x);
            }
        }

        const float* __restrict__ bpA =
            bias_b + ((size_t)(a0 + aA) << 14) + (size_t)browA * 128;
        const float* __restrict__ bpB = bpA + (1 << 14);
        float psA0 = 0.f, psA1 = 0.f, pmA0 = -1e30f, pmA1 = -1e30f;
        float psB0 = 0.f, psB1 = 0.f, pmB0 = -1e30f, pmB1 = -1e30f;

        float2 nA0 = *(const float2*)&bpA[colbase];
        float2 nA1 = *(const float2*)&bpA[8 * 128 + colbase];
        float2 nB0 = *(const float2*)&bpB[colbase];
        float2 nB1 = *(const float2*)&bpB[8 * 128 + colbase];

#pragma unroll 2
        for (int nc = 0; nc < 16; nc++) {
            float2 bA0 = nA0, bA1 = nA1, bB0 = nB0, bB1 = nB1;
            if (nc < 15) {
                const int col = (nc + 1) * 8 + colbase;
                nA0 = *(const float2*)&bpA[col];
                nA1 = *(const float2*)&bpA[8 * 128 + col];
                nB0 = *(const float2*)&bpB[col];
                nB1 = *(const float2*)&bpB[8 * 128 + col];
            }
            uint32_t b[8];
            ldmatrix_x4(b[0], b[1], b[2], b[3], v_ld + nc * (8 * ROWB));
            ldmatrix_x4(b[4], b[5], b[6], b[7], v_ld + nc * (8 * ROWB) + 64);
            // 4 independent depth-2 accumulator chains
            float c0a[4] = {0.f, 0.f, 0.f, 0.f};
            float c0b[4] = {0.f, 0.f, 0.f, 0.f};
            float c1a[4] = {0.f, 0.f, 0.f, 0.f};
            float c1b[4] = {0.f, 0.f, 0.f, 0.f};
            mma_f16(c0a, fa0[0],  fa0[1],  fa0[2],  fa0[3],  b[0], b[1]);
            mma_f16(c1a, fa1[0],  fa1[1],  fa1[2],  fa1[3],  b[0], b[1]);
            mma_f16(c0b, fa0[4],  fa0[5],  fa0[6],  fa0[7],  b[2], b[3]);
            mma_f16(c1b, fa1[4],  fa1[5],  fa1[6],  fa1[7],  b[2], b[3]);
            mma_f16(c0a, fa0[8],  fa0[9],  fa0[10], fa0[11], b[4], b[5]);
            mma_f16(c1a, fa1[8],  fa1[9],  fa1[10], fa1[11], b[4], b[5]);
            mma_f16(c0b, fa0[12], fa0[13], fa0[14], fa0[15], b[6], b[7]);
            mma_f16(c1b, fa1[12], fa1[13], fa1[14], fa1[15], b[6], b[7]);
            {
                float s0 = (c0a[0] + c0b[0]) + bA0.x;
                float s1 = (c0a[1] + c0b[1]) + bA0.y;
                float s2 = (c0a[2] + c0b[2]) + bA1.x;
                float s3 = (c0a[3] + c0b[3]) + bA1.y;
                psA0 += s0 + s1; psA1 += s2 + s3;
                pmA0 = fmaxf(pmA0, fmaxf(s0, s1));
                pmA1 = fmaxf(pmA1, fmaxf(s2, s3));
            }
            {
                float s0 = (c1a[0] + c1b[0]) + bB0.x;
                float s1 = (c1a[1] + c1b[1]) + bB0.y;
                float s2 = (c1a[2] + c1b[2]) + bB1.x;
                float s3 = (c1a[3] + c1b[3]) + bB1.y;
                psB0 += s0 + s1; psB1 += s2 + s3;
                pmB0 = fmaxf(pmB0, fmaxf(s0, s1));
                pmB1 = fmaxf(pmB1, fmaxf(s2, s3));
            }
        }
#pragma unroll
        for (int off = 1; off <= 2; off <<= 1) {
            psA0 += __shfl_xor_sync(0xffffffffu, psA0, off);
            psA1 += __shfl_xor_sync(0xffffffffu, psA1, off);
            psB0 += __shfl_xor_sync(0xffffffffu, psB0, off);
            psB1 += __shfl_xor_sync(0xffffffffu, psB1, off);
            pmA0 = fmaxf(pmA0, __shfl_xor_sync(0xffffffffu, pmA0, off));
            pmA1 = fmaxf(pmA1, __shfl_xor_sync(0xffffffffu, pmA1, off));
            pmB0 = fmaxf(pmB0, __shfl_xor_sync(0xffffffffu, pmB0, off));
            pmB1 = fmaxf(pmB1, __shfl_xor_sync(0xffffffffu, pmB1, off));
        }
        if (tig == 0) {
            fused[aA * 128 + browA]     = psA0 * (1.0f / 128.0f) + pmA0;
            fused[aA * 128 + browA + 8] = psA1 * (1.0f / 128.0f) + pmA1;
            fused[aB * 128 + browA]     = psB0 * (1.0f / 128.0f) + pmB0;
            fused[aB * 128 + browA + 8] = psB1 * (1.0f / 128.0f) + pmB1;
        }
    }
    __syncthreads();

    for (int a = wid; a < 64; a += 16) {
        float4 fv = *(float4*)&fused[a * 128 + lane * 4];
        float m = fmaxf(fmaxf(fv.x, fv.y), fmaxf(fv.z, fv.w));
#pragma unroll
        for (int off = 16; off >= 1; off >>= 1)
            m = fmaxf(m, __shfl_xor_sync(0xffffffffu, m, off));
        float e0 = __expf(fv.x - m), e1 = __expf(fv.y - m);
        float e2 = __expf(fv.z - m), e3 = __expf(fv.w - m);
        float s = (e0 + e1) + (e2 + e3);
#pragma unroll
        for (int off = 16; off >= 1; off >>= 1)
            s += __shfl_xor_sync(0xffffffffu, s, off);
        float inv = 1.0f / s;
        *(float4*)&fused[a * 128 + lane * 4] =
            make_float4(e0 * inv, e1 * inv, e2 * inv, e3 * inv);
    }
    __syncthreads();

    {
        int a = tid >> 3;
        int dg = (tid & 7) * 8;
        float o[8];
#pragma unroll
        for (int j = 0; j < 8; j++) o[j] = 0.f;
        const float* wrow = fused + a * 128;
#pragma unroll 4
        for (int b = 0; b < 128; b++) {
            float wb = wrow[b];
            const float* qr = qs + b * 64 + dg;
            float4 q0 = *(const float4*)&qr[0];
            float4 q1 = *(const float4*)&qr[4];
            o[0] += wb * q0.x; o[1] += wb * q0.y;
            o[2] += wb * q0.z; o[3] += wb * q0.w;
            o[4] += wb * q1.x; o[5] += wb * q1.y;
            o[6] += wb * q1.z; o[7] += wb * q1.w;
        }
        int t = a0 + a;
        float* dst = g_attn2 + ((size_t)t * 8 + batch) * 512 + head * 64 + dg;
        *(float4*)&dst[0] = make_float4(o[0], o[1], o[2], o[3]);
        *(float4*)&dst[4] = make_float4(o[4], o[5], o[6], o[7]);
    }
}

// ---------------------------------------------------------------------------
extern "C" void kernel_launch(void* const* d_in, const int* in_sizes, int n_in,
                              void* d_out, int out_size)
{
    const float* query = (const float*)d_in[0];
    const float* key   = (const float*)d_in[1];
    const float* value = (const float*)d_in[2];
    const float* cbias = (const float*)d_in[3];
    const float* ipw   = (const float*)d_in[4];
    const float* ipb   = (const float*)d_in[5];
    const float* outw  = (const float*)d_in[6];
    const float* outb  = (const float*)d_in[7];
    float* out = (float*)d_out;

    // in-projection: R9 version (fastest measured)
    proj_in_kernel<<<dim3(24, 16), 128>>>(query, key, value, ipw, ipb);

    cudaFuncSetAttribute(tri_main_v10,
                         cudaFuncAttributeMaxDynamicSharedMemorySize, SM_TOTAL);
    tri_main_v10<<<dim3(8, 2, 8), 512, SM_TOTAL>>>(cbias);

    // out-projection: R11 K-split version (measured good)
    cudaFuncSetAttribute(proj_out_kernel,
                         cudaFuncAttributeMaxDynamicSharedMemorySize, PO_TOTAL);
    proj_out_kernel<<<dim3(8, 16), 256, PO_TOTAL>>>(outw, outb, out);
}